// round 10
// baseline (speedup 1.0000x reference)
#include <cuda_runtime.h>
#include <cuda_bf16.h>
#include <math.h>

#define N_FFT 16000
#define M_HALF 8000
#define BATCH 512
#define IN_DIM 2048
#define NTH 1024

// ---------------- scratch (static __device__, no allocation) ----------------
__device__ int    g_h[2 * IN_DIM];
__device__ float  g_s[2 * IN_DIM];
__device__ float2 g_tw[N_FFT];      // W_N^j = exp(-2*pi*i*j/N)
__device__ int    g_isig[N_FFT];    // natural freq -> scrambled pos (plan 16,10,10,10)
__device__ int    g_isig8[M_HALF];  // natural freq -> scrambled pos (plan 16,10,10,5)
__device__ __align__(16) float g_norm[N_FFT];  // sum |c| (column sumsq)

// ---------------- complex helpers ----------------
__device__ __forceinline__ float2 cmul(float2 a, float2 b) {
    return make_float2(a.x * b.x - a.y * b.y, a.x * b.y + a.y * b.x);
}
__device__ __forceinline__ float2 cmulc(float2 a, float2 b) {  // a * conj(b)
    return make_float2(a.x * b.x + a.y * b.y, a.y * b.x - a.x * b.y);
}
__device__ __forceinline__ float2 cadd(float2 a, float2 b) {
    return make_float2(a.x + b.x, a.y + b.y);
}
__device__ __forceinline__ float2 csub(float2 a, float2 b) {
    return make_float2(a.x - b.x, a.y - b.y);
}
__device__ __forceinline__ float2 mul_negi(float2 a) { return make_float2(a.y, -a.x); }
__device__ __forceinline__ float2 mul_posi(float2 a) { return make_float2(-a.y, a.x); }

// W5^j
__constant__ float2 W5c[5] = {
    { 1.0f,                  0.0f                 },
    { 0.30901699437494742f, -0.95105651629515357f },
    {-0.80901699437494742f, -0.58778525229247314f },
    {-0.80901699437494745f,  0.58778525229247312f },
    { 0.30901699437494740f,  0.95105651629515364f }
};
// W10^m, m=0..4
__constant__ float2 W10c[5] = {
    { 1.0f,                  0.0f                 },
    { 0.80901699437494742f, -0.58778525229247312f },
    { 0.30901699437494742f, -0.95105651629515357f },
    {-0.30901699437494742f, -0.95105651629515357f },
    {-0.80901699437494742f, -0.58778525229247312f }
};

#define C_S2 0.70710678118654752440f
#define C16A 0.92387953251128676f
#define C16B 0.38268343236508977f

// ---------------- small DFTs in registers ----------------
#define DFT4F(a,b,c,d,o0,o1,o2,o3) do { \
    float2 _t0 = cadd(a,c), _t1 = csub(a,c); \
    float2 _t2 = cadd(b,d), _t3 = mul_negi(csub(b,d)); \
    o0 = cadd(_t0,_t2); o1 = cadd(_t1,_t3); \
    o2 = csub(_t0,_t2); o3 = csub(_t1,_t3); } while(0)
#define DFT4I(a,b,c,d,o0,o1,o2,o3) do { \
    float2 _t0 = cadd(a,c), _t1 = csub(a,c); \
    float2 _t2 = cadd(b,d), _t3 = mul_posi(csub(b,d)); \
    o0 = cadd(_t0,_t2); o1 = cadd(_t1,_t3); \
    o2 = csub(_t0,_t2); o3 = csub(_t1,_t3); } while(0)

__device__ __forceinline__ void dft16(float2 x[16]) {
    float2 A0[4], A1[4], A2[4], A3[4];
    DFT4F(x[0], x[4], x[8],  x[12], A0[0], A0[1], A0[2], A0[3]);
    DFT4F(x[1], x[5], x[9],  x[13], A1[0], A1[1], A1[2], A1[3]);
    DFT4F(x[2], x[6], x[10], x[14], A2[0], A2[1], A2[2], A2[3]);
    DFT4F(x[3], x[7], x[11], x[15], A3[0], A3[1], A3[2], A3[3]);
    A1[1] = cmul(A1[1], make_float2( C16A, -C16B));
    A1[2] = cmul(A1[2], make_float2( C_S2, -C_S2));
    A1[3] = cmul(A1[3], make_float2( C16B, -C16A));
    A2[1] = cmul(A2[1], make_float2( C_S2, -C_S2));
    A2[2] = mul_negi(A2[2]);
    A2[3] = cmul(A2[3], make_float2(-C_S2, -C_S2));
    A3[1] = cmul(A3[1], make_float2( C16B, -C16A));
    A3[2] = cmul(A3[2], make_float2(-C_S2, -C_S2));
    A3[3] = cmul(A3[3], make_float2(-C16A,  C16B));
#pragma unroll
    for (int m = 0; m < 4; m++)
        DFT4F(A0[m], A1[m], A2[m], A3[m], x[m], x[m+4], x[m+8], x[m+12]);
}

__device__ __forceinline__ void idft16(float2 x[16]) {
    float2 A0[4], A1[4], A2[4], A3[4];
    DFT4I(x[0], x[4], x[8],  x[12], A0[0], A0[1], A0[2], A0[3]);
    DFT4I(x[1], x[5], x[9],  x[13], A1[0], A1[1], A1[2], A1[3]);
    DFT4I(x[2], x[6], x[10], x[14], A2[0], A2[1], A2[2], A2[3]);
    DFT4I(x[3], x[7], x[11], x[15], A3[0], A3[1], A3[2], A3[3]);
    A1[1] = cmul(A1[1], make_float2( C16A,  C16B));
    A1[2] = cmul(A1[2], make_float2( C_S2,  C_S2));
    A1[3] = cmul(A1[3], make_float2( C16B,  C16A));
    A2[1] = cmul(A2[1], make_float2( C_S2,  C_S2));
    A2[2] = mul_posi(A2[2]);
    A2[3] = cmul(A2[3], make_float2(-C_S2,  C_S2));
    A3[1] = cmul(A3[1], make_float2( C16B,  C16A));
    A3[2] = cmul(A3[2], make_float2(-C_S2,  C_S2));
    A3[3] = cmul(A3[3], make_float2(-C16A, -C16B));
#pragma unroll
    for (int m = 0; m < 4; m++)
        DFT4I(A0[m], A1[m], A2[m], A3[m], x[m], x[m+4], x[m+8], x[m+12]);
}

__device__ __forceinline__ void dft5f(float2 a0, float2 a1, float2 a2,
                                      float2 a3, float2 a4, float2 o[5]) {
#pragma unroll
    for (int p = 0; p < 5; p++) {
        float2 acc = a0;
        acc = cadd(acc, cmul(a1, W5c[p % 5]));
        acc = cadd(acc, cmul(a2, W5c[(2*p) % 5]));
        acc = cadd(acc, cmul(a3, W5c[(3*p) % 5]));
        acc = cadd(acc, cmul(a4, W5c[(4*p) % 5]));
        o[p] = acc;
    }
}
__device__ __forceinline__ void dft5i(float2 a0, float2 a1, float2 a2,
                                      float2 a3, float2 a4, float2 o[5]) {
#pragma unroll
    for (int p = 0; p < 5; p++) {
        float2 acc = a0;
        acc = cadd(acc, cmulc(a1, W5c[p % 5]));
        acc = cadd(acc, cmulc(a2, W5c[(2*p) % 5]));
        acc = cadd(acc, cmulc(a3, W5c[(3*p) % 5]));
        acc = cadd(acc, cmulc(a4, W5c[(4*p) % 5]));
        o[p] = acc;
    }
}

__device__ __forceinline__ void dft10(float2 x[10]) {
    float2 B0[5], B1[5];
    dft5f(x[0], x[2], x[4], x[6], x[8], B0);
    dft5f(x[1], x[3], x[5], x[7], x[9], B1);
#pragma unroll
    for (int m = 0; m < 5; m++) {
        float2 t = cmul(B1[m], W10c[m]);
        x[m]     = cadd(B0[m], t);
        x[m + 5] = csub(B0[m], t);
    }
}
__device__ __forceinline__ void idft10(float2 x[10]) {
    float2 B0[5], B1[5];
    dft5i(x[0], x[2], x[4], x[6], x[8], B0);
    dft5i(x[1], x[3], x[5], x[7], x[9], B1);
#pragma unroll
    for (int m = 0; m < 5; m++) {
        float2 t = cmulc(B1[m], W10c[m]);
        x[m]     = cadd(B0[m], t);
        x[m + 5] = csub(B0[m], t);
    }
}

// ---------------- forward FFT stages, 16000 pts (plan: 16,10,10,10) --------
// Direct twiddle indexing (independent L1 loads; no serial cmul chains).

__device__ __forceinline__ void stage16_fwd(float2* sm) {
    const int h = 1000;
    for (int t = threadIdx.x; t < h; t += NTH) {
        float2* b = sm + t;
        float2 x[16];
#pragma unroll
        for (int q = 0; q < 16; q++) x[q] = b[q * h];
        dft16(x);
        b[0] = x[0];
#pragma unroll
        for (int p = 1; p < 16; p++) b[p * h] = cmul(x[p], g_tw[t * p]);
    }
    __syncthreads();
}

template<int NS, int STRIDE>
__device__ __forceinline__ void stage10_fwd(float2* sm) {
    const int h = NS / 10;
    for (int u = threadIdx.x; u < N_FFT / 10; u += NTH) {
        int blk = u / h, t = u - blk * h;
        float2* b = sm + blk * NS + t;
        float2 x[10];
#pragma unroll
        for (int q = 0; q < 10; q++) x[q] = b[q * h];
        dft10(x);
        b[0] = x[0];
        if (NS != 10) {
#pragma unroll
            for (int p = 1; p < 10; p++)
                b[p * h] = cmul(x[p], g_tw[STRIDE * t * p]);
        } else {
#pragma unroll
            for (int p = 1; p < 10; p++) b[p * h] = x[p];
        }
    }
    __syncthreads();
}

// ---------------- inverse FFT stages, 8000 pts (plan: 16,10,10,5) ----------
// Mirrored DIT, scrambled input -> natural order. W_8000^j = g_tw[2j].

__device__ __forceinline__ void stage5_inv8(float2* Y) {
    for (int u = threadIdx.x; u < M_HALF / 5; u += NTH) {
        float2* b = Y + u * 5;
        float2 o[5];
        dft5i(b[0], b[1], b[2], b[3], b[4], o);
#pragma unroll
        for (int q = 0; q < 5; q++) b[q] = o[q];
    }
    __syncthreads();
}

template<int NS, int TWS>   // TWS = 16000 / NS (half-size doubling folded in)
__device__ __forceinline__ void stage10_inv8(float2* Y) {
    const int h = NS / 10;
    for (int u = threadIdx.x; u < M_HALF / 10; u += NTH) {
        int blk = u / h, t = u - blk * h;
        float2* b = Y + blk * NS + t;
        float2 y[10];
        y[0] = b[0];
#pragma unroll
        for (int p = 1; p < 10; p++) y[p] = cmulc(b[p * h], g_tw[TWS * t * p]);
        idft10(y);
#pragma unroll
        for (int q = 0; q < 10; q++) b[q * h] = y[q];
    }
    __syncthreads();
}

// Final inverse stage (radix-16 over 8000) fused with de-interleave,
// signed-sqrt output (coalesced float2 stores) and column-norm REDG.
__device__ __forceinline__ void stage16_inv_store8(float2* Y, float* dst) {
    const int h = 500;
    float2* dst2 = (float2*)dst;
    for (int t = threadIdx.x; t < h; t += NTH) {
        float2* b = Y + t;
        float2 y[16];
        y[0] = b[0];
#pragma unroll
        for (int p = 1; p < 16; p++) y[p] = cmulc(b[p * h], g_tw[2 * t * p]);
        idft16(y);
#pragma unroll
        for (int q = 0; q < 16; q++) {
            int m = q * 500 + t;           // y[m] = x[2m] + i x[2m+1]
            float c0 = y[q].x, c1 = y[q].y;
            float a0 = fabsf(c0), a1 = fabsf(c1);
            dst2[m] = make_float2(copysignf(sqrtf(a0), c0),
                                  copysignf(sqrtf(a1), c1));
            atomicAdd(&g_norm[2 * m],     a0);   // ss^2 == |c| exactly
            atomicAdd(&g_norm[2 * m + 1], a1);
        }
    }
}

// ------- extract (one block per sketch row) + fused one-time setup ---------
__global__ void k_extract(const float* __restrict__ sk1,
                          const float* __restrict__ sk2) {
    int r = blockIdx.x;

    if (threadIdx.x < 4) {
        int j = r * 4 + threadIdx.x;
        if (j < N_FFT) {
            double a = -2.0 * 3.14159265358979323846 * (double)j / (double)N_FFT;
            double sn, cs;
            sincos(a, &sn, &cs);
            g_tw[j] = make_float2((float)cs, (float)sn);
            g_norm[j] = 0.f;
            // isig for plan {16,10,10,10}
            int p0 = j / 1000, rr = j - p0 * 1000;
            int p1 = rr / 100;  rr -= p1 * 100;
            int p2 = rr / 10,  p3 = rr - (rr / 10) * 10;
            g_isig[p0 + 16 * (p1 + 10 * (p2 + 10 * p3))] = j;
            if (j < M_HALF) {
                // isig8 for plan {16,10,10,5}
                int q0 = j / 500, r8 = j - q0 * 500;
                int q1 = r8 / 50; r8 -= q1 * 50;
                int q2 = r8 / 5,  q3 = r8 - q2 * 5;
                g_isig8[q0 + 16 * (q1 + 10 * (q2 + 10 * q3))] = j;
            }
        }
    }

    const float* row = (r < IN_DIM) ? (sk1 + (size_t)r * N_FFT)
                                    : (sk2 + (size_t)(r - IN_DIM) * N_FFT);
    const float4* row4 = (const float4*)row;
    __shared__ int found;
    if (threadIdx.x == 0) found = 0;
    __syncthreads();
    for (int base = 0; base < N_FFT / 4; base += blockDim.x) {
        int j = base + threadIdx.x;
        if (j < N_FFT / 4) {
            float4 v = row4[j];
            if (v.x != 0.f || v.y != 0.f || v.z != 0.f || v.w != 0.f) {
                int   c   = (v.x != 0.f) ? 0 : (v.y != 0.f) ? 1 : (v.z != 0.f) ? 2 : 3;
                float val = (c == 0) ? v.x : (c == 1) ? v.y : (c == 2) ? v.z : v.w;
                g_h[r] = 4 * j + c;
                g_s[r] = val;
                found = 1;
            }
        }
        __syncthreads();
        if (found) break;
    }
}

// ---------------- fused main kernel ----------------
// smem: [0,16000) Z work array, [16000,24000) Y half-spectrum. 192000 bytes.
__global__ void __launch_bounds__(NTH, 1)
k_main(const float* __restrict__ x1, const float* __restrict__ x2,
       float* __restrict__ out) {
    extern __shared__ float2 sm[];
    float2* Y = sm + N_FFT;
    int b = blockIdx.x;

    float4* sm4 = (float4*)sm;
    for (int i = threadIdx.x; i < N_FFT / 2; i += NTH)
        sm4[i] = make_float4(0.f, 0.f, 0.f, 0.f);
    __syncthreads();

    // count-sketch scatter: p1 -> real, p2 -> imag
    const float* r1 = x1 + (size_t)b * IN_DIM;
    const float* r2 = x2 + (size_t)b * IN_DIM;
    for (int k = threadIdx.x; k < IN_DIM; k += NTH) {
        atomicAdd(&sm[g_h[k]].x,          g_s[k]          * r1[k]);
        atomicAdd(&sm[g_h[IN_DIM + k]].y, g_s[IN_DIM + k] * r2[k]);
    }
    __syncthreads();

    // forward 16000-pt FFT of z = p1 + i p2 (scrambled output)
    stage16_fwd(sm);
    stage10_fwd<1000, 16>(sm);
    stage10_fwd<100, 160>(sm);
    stage10_fwd<10, 1600>(sm);

    // Hermitian split + product + irfft half-size packing, all in one pass.
    // Y[k] = (G[k]+G[k+8000]) + i (G[k]-G[k+8000]) e^{+2pi i k/N},
    // G[k+8000] = conj(G[8000-k]).  Writes go to the scrambled order of the
    // 8000-pt inverse plan. Z reads and Y writes live in disjoint smem.
    for (int k = threadIdx.x; k <= 4000; k += NTH) {
        if (k == 0) {
            float2 z0 = sm[g_isig[0]];
            float2 zn = sm[g_isig[M_HALF]];
            float G0 = z0.x * z0.y;         // F1[0]*F2[0]
            float G8 = zn.x * zn.y;         // F1[8000]*F2[8000]
            Y[g_isig8[0]] = make_float2(G0 + G8, G0 - G8);
        } else if (k == 4000) {
            float2 Zk = sm[g_isig[4000]], Zm = sm[g_isig[12000]];
            float2 F1 = make_float2(0.5f*(Zk.x+Zm.x),  0.5f*(Zk.y-Zm.y));
            float2 F2 = make_float2(0.5f*(Zk.y+Zm.y), -0.5f*(Zk.x-Zm.x));
            float2 G = cmul(F1, F2);
            Y[g_isig8[4000]] = make_float2(2.f * G.x, -2.f * G.y);
        } else {
            int mk = M_HALF - k;
            float2 Zk  = sm[g_isig[k]],  Zmk = sm[g_isig[N_FFT - k]];
            float2 Za  = sm[g_isig[mk]], Zb  = sm[g_isig[M_HALF + k]];
            float2 F1 = make_float2(0.5f*(Zk.x+Zmk.x),  0.5f*(Zk.y-Zmk.y));
            float2 F2 = make_float2(0.5f*(Zk.y+Zmk.y), -0.5f*(Zk.x-Zmk.x));
            float2 Gk = cmul(F1, F2);
            float2 H1 = make_float2(0.5f*(Za.x+Zb.x),  0.5f*(Za.y-Zb.y));
            float2 H2 = make_float2(0.5f*(Za.y+Zb.y), -0.5f*(Za.x-Zb.x));
            float2 Gm = cmul(H1, H2);
            float2 W  = g_tw[k];
            float2 cGm = make_float2(Gm.x, -Gm.y);
            float2 cGk = make_float2(Gk.x, -Gk.y);
            // Y[k]
            float2 A1 = cadd(Gk, cGm);
            float2 B1 = cmulc(csub(Gk, cGm), W);           // * e^{+2pi i k/N}
            Y[g_isig8[k]] = cadd(A1, mul_posi(B1));
            // Y[8000-k]  (e^{+2pi i mk/N} = -W)
            float2 A2 = cadd(Gm, cGk);
            float2 t2 = cmul(csub(Gm, cGk), W);
            Y[g_isig8[mk]] = cadd(A2, mul_posi(make_float2(-t2.x, -t2.y)));
        }
    }
    __syncthreads();

    // 8000-pt inverse (natural order out) fused with de-interleave + store
    stage5_inv8(Y);
    stage10_inv8<50, 320>(Y);
    stage10_inv8<500, 32>(Y);
    stage16_inv_store8(Y, out + (size_t)b * N_FFT);
}

// fused: reciprocal-norm computed in place from the accumulated sums
__global__ void k_normalize(float* __restrict__ out) {
    int c4 = blockIdx.x * blockDim.x + threadIdx.x;
    if (c4 >= N_FFT / 4) return;
    int b = blockIdx.y;
    float4 nv = ((const float4*)g_norm)[c4];
    float rx = 1.0f / fmaxf(sqrtf(nv.x), 1e-12f);
    float ry = 1.0f / fmaxf(sqrtf(nv.y), 1e-12f);
    float rz = 1.0f / fmaxf(sqrtf(nv.z), 1e-12f);
    float rw = 1.0f / fmaxf(sqrtf(nv.w), 1e-12f);
    float4* o4 = (float4*)out + (size_t)b * (N_FFT / 4) + c4;
    float4 v = *o4;
    v.x *= rx; v.y *= ry; v.z *= rz; v.w *= rw;
    *o4 = v;
}

// ---------------- launch ----------------
extern "C" void kernel_launch(void* const* d_in, const int* in_sizes, int n_in,
                              void* d_out, int out_size) {
    const float* x1  = (const float*)d_in[0];
    const float* x2  = (const float*)d_in[1];
    const float* sk1 = (const float*)d_in[2];
    const float* sk2 = (const float*)d_in[3];
    float* out = (float*)d_out;

    const int smem = (N_FFT + M_HALF) * sizeof(float2);  // 192000 B
    cudaFuncSetAttribute(k_main, cudaFuncAttributeMaxDynamicSharedMemorySize, smem);

    k_extract<<<2 * IN_DIM, 512>>>(sk1, sk2);
    k_main<<<BATCH, NTH, smem>>>(x1, x2, out);
    dim3 ng((N_FFT / 4 + 255) / 256, BATCH);
    k_normalize<<<ng, 256>>>(out);
}

// round 11
// speedup vs baseline: 1.3441x; 1.3441x over previous
#include <cuda_runtime.h>
#include <cuda_bf16.h>
#include <math.h>

#define N_FFT 16000
#define M_HALF 8000
#define BATCH 512
#define IN_DIM 2048
#define NTH 1024

// ---------------- scratch (static __device__, no allocation) ----------------
__device__ int    g_h[2 * IN_DIM];
__device__ float  g_s[2 * IN_DIM];
__device__ float2 g_tw[N_FFT];      // W_N^j = exp(-2*pi*i*j/N)
__device__ int    g_isig[N_FFT];    // natural freq -> scrambled pos (plan 16,10,10,10)
__device__ int    g_isig8[M_HALF];  // natural freq -> scrambled pos (plan 16,10,10,5)
__device__ __align__(16) float g_norm[N_FFT];  // sum |c| (column sumsq)

// ---------------- complex helpers ----------------
__device__ __forceinline__ float2 cmul(float2 a, float2 b) {
    return make_float2(a.x * b.x - a.y * b.y, a.x * b.y + a.y * b.x);
}
__device__ __forceinline__ float2 cmulc(float2 a, float2 b) {  // a * conj(b)
    return make_float2(a.x * b.x + a.y * b.y, a.y * b.x - a.x * b.y);
}
__device__ __forceinline__ float2 cadd(float2 a, float2 b) {
    return make_float2(a.x + b.x, a.y + b.y);
}
__device__ __forceinline__ float2 csub(float2 a, float2 b) {
    return make_float2(a.x - b.x, a.y - b.y);
}
__device__ __forceinline__ float2 mul_negi(float2 a) { return make_float2(a.y, -a.x); }
__device__ __forceinline__ float2 mul_posi(float2 a) { return make_float2(-a.y, a.x); }

// W5^j
__constant__ float2 W5c[5] = {
    { 1.0f,                  0.0f                 },
    { 0.30901699437494742f, -0.95105651629515357f },
    {-0.80901699437494742f, -0.58778525229247314f },
    {-0.80901699437494745f,  0.58778525229247312f },
    { 0.30901699437494740f,  0.95105651629515364f }
};
// W10^m, m=0..4
__constant__ float2 W10c[5] = {
    { 1.0f,                  0.0f                 },
    { 0.80901699437494742f, -0.58778525229247312f },
    { 0.30901699437494742f, -0.95105651629515357f },
    {-0.30901699437494742f, -0.95105651629515357f },
    {-0.80901699437494742f, -0.58778525229247312f }
};

#define C_S2 0.70710678118654752440f
#define C16A 0.92387953251128676f
#define C16B 0.38268343236508977f

// ---------------- small DFTs in registers ----------------
#define DFT4F(a,b,c,d,o0,o1,o2,o3) do { \
    float2 _t0 = cadd(a,c), _t1 = csub(a,c); \
    float2 _t2 = cadd(b,d), _t3 = mul_negi(csub(b,d)); \
    o0 = cadd(_t0,_t2); o1 = cadd(_t1,_t3); \
    o2 = csub(_t0,_t2); o3 = csub(_t1,_t3); } while(0)
#define DFT4I(a,b,c,d,o0,o1,o2,o3) do { \
    float2 _t0 = cadd(a,c), _t1 = csub(a,c); \
    float2 _t2 = cadd(b,d), _t3 = mul_posi(csub(b,d)); \
    o0 = cadd(_t0,_t2); o1 = cadd(_t1,_t3); \
    o2 = csub(_t0,_t2); o3 = csub(_t1,_t3); } while(0)

__device__ __forceinline__ void dft16(float2 x[16]) {
    float2 A0[4], A1[4], A2[4], A3[4];
    DFT4F(x[0], x[4], x[8],  x[12], A0[0], A0[1], A0[2], A0[3]);
    DFT4F(x[1], x[5], x[9],  x[13], A1[0], A1[1], A1[2], A1[3]);
    DFT4F(x[2], x[6], x[10], x[14], A2[0], A2[1], A2[2], A2[3]);
    DFT4F(x[3], x[7], x[11], x[15], A3[0], A3[1], A3[2], A3[3]);
    A1[1] = cmul(A1[1], make_float2( C16A, -C16B));
    A1[2] = cmul(A1[2], make_float2( C_S2, -C_S2));
    A1[3] = cmul(A1[3], make_float2( C16B, -C16A));
    A2[1] = cmul(A2[1], make_float2( C_S2, -C_S2));
    A2[2] = mul_negi(A2[2]);
    A2[3] = cmul(A2[3], make_float2(-C_S2, -C_S2));
    A3[1] = cmul(A3[1], make_float2( C16B, -C16A));
    A3[2] = cmul(A3[2], make_float2(-C_S2, -C_S2));
    A3[3] = cmul(A3[3], make_float2(-C16A,  C16B));
#pragma unroll
    for (int m = 0; m < 4; m++)
        DFT4F(A0[m], A1[m], A2[m], A3[m], x[m], x[m+4], x[m+8], x[m+12]);
}

__device__ __forceinline__ void idft16(float2 x[16]) {
    float2 A0[4], A1[4], A2[4], A3[4];
    DFT4I(x[0], x[4], x[8],  x[12], A0[0], A0[1], A0[2], A0[3]);
    DFT4I(x[1], x[5], x[9],  x[13], A1[0], A1[1], A1[2], A1[3]);
    DFT4I(x[2], x[6], x[10], x[14], A2[0], A2[1], A2[2], A2[3]);
    DFT4I(x[3], x[7], x[11], x[15], A3[0], A3[1], A3[2], A3[3]);
    A1[1] = cmul(A1[1], make_float2( C16A,  C16B));
    A1[2] = cmul(A1[2], make_float2( C_S2,  C_S2));
    A1[3] = cmul(A1[3], make_float2( C16B,  C16A));
    A2[1] = cmul(A2[1], make_float2( C_S2,  C_S2));
    A2[2] = mul_posi(A2[2]);
    A2[3] = cmul(A2[3], make_float2(-C_S2,  C_S2));
    A3[1] = cmul(A3[1], make_float2( C16B,  C16A));
    A3[2] = cmul(A3[2], make_float2(-C_S2,  C_S2));
    A3[3] = cmul(A3[3], make_float2(-C16A, -C16B));
#pragma unroll
    for (int m = 0; m < 4; m++)
        DFT4I(A0[m], A1[m], A2[m], A3[m], x[m], x[m+4], x[m+8], x[m+12]);
}

__device__ __forceinline__ void dft5f(float2 a0, float2 a1, float2 a2,
                                      float2 a3, float2 a4, float2 o[5]) {
#pragma unroll
    for (int p = 0; p < 5; p++) {
        float2 acc = a0;
        acc = cadd(acc, cmul(a1, W5c[p % 5]));
        acc = cadd(acc, cmul(a2, W5c[(2*p) % 5]));
        acc = cadd(acc, cmul(a3, W5c[(3*p) % 5]));
        acc = cadd(acc, cmul(a4, W5c[(4*p) % 5]));
        o[p] = acc;
    }
}
__device__ __forceinline__ void dft5i(float2 a0, float2 a1, float2 a2,
                                      float2 a3, float2 a4, float2 o[5]) {
#pragma unroll
    for (int p = 0; p < 5; p++) {
        float2 acc = a0;
        acc = cadd(acc, cmulc(a1, W5c[p % 5]));
        acc = cadd(acc, cmulc(a2, W5c[(2*p) % 5]));
        acc = cadd(acc, cmulc(a3, W5c[(3*p) % 5]));
        acc = cadd(acc, cmulc(a4, W5c[(4*p) % 5]));
        o[p] = acc;
    }
}

__device__ __forceinline__ void dft10(float2 x[10]) {
    float2 B0[5], B1[5];
    dft5f(x[0], x[2], x[4], x[6], x[8], B0);
    dft5f(x[1], x[3], x[5], x[7], x[9], B1);
#pragma unroll
    for (int m = 0; m < 5; m++) {
        float2 t = cmul(B1[m], W10c[m]);
        x[m]     = cadd(B0[m], t);
        x[m + 5] = csub(B0[m], t);
    }
}
__device__ __forceinline__ void idft10(float2 x[10]) {
    float2 B0[5], B1[5];
    dft5i(x[0], x[2], x[4], x[6], x[8], B0);
    dft5i(x[1], x[3], x[5], x[7], x[9], B1);
#pragma unroll
    for (int m = 0; m < 5; m++) {
        float2 t = cmulc(B1[m], W10c[m]);
        x[m]     = cadd(B0[m], t);
        x[m + 5] = csub(B0[m], t);
    }
}

// ---------------- split twiddle tables: 2 loads, depth <= 3 ----------------
// radix-16: p = 4a+b, tw^p = Q[a] * P[b], P from g_tw[s], Q from g_tw[4s]
struct Tw16 {
    float2 P1, P2, P3, Q1, Q2, Q3;
    __device__ __forceinline__ void init(int s) {
        P1 = g_tw[s];  Q1 = g_tw[4 * s];
        P2 = cmul(P1, P1); P3 = cmul(P2, P1);
        Q2 = cmul(Q1, Q1); Q3 = cmul(Q2, Q1);
    }
    __device__ __forceinline__ float2 get(int p) const {   // p in 1..15 (constant)
        int a = p >> 2, bb = p & 3;
        float2 Pb = (bb == 1) ? P1 : (bb == 2) ? P2 : P3;
        float2 Qa = (a  == 1) ? Q1 : (a  == 2) ? Q2 : Q3;
        if (a == 0)  return Pb;
        if (bb == 0) return Qa;
        return cmul(Qa, Pb);
    }
};
// radix-10: p = 5a+b, tw^p = (a? Q1:1) * P[b], P from g_tw[s], Q1 = g_tw[5s]
struct Tw10 {
    float2 P1, P2, P3, P4, Q1;
    __device__ __forceinline__ void init(int s) {
        P1 = g_tw[s];  Q1 = g_tw[5 * s];
        P2 = cmul(P1, P1); P3 = cmul(P2, P1); P4 = cmul(P2, P2);
    }
    __device__ __forceinline__ float2 get(int p) const {   // p in 1..9 (constant)
        int a = p / 5, bb = p % 5;
        float2 Pb = (bb == 1) ? P1 : (bb == 2) ? P2 : (bb == 3) ? P3 : P4;
        if (a == 0)  return Pb;
        if (bb == 0) return Q1;
        return cmul(Q1, Pb);
    }
};

// ---------------- forward FFT stages, 16000 pts (plan: 16,10,10,10) --------
__device__ __forceinline__ void stage16_fwd(float2* sm) {
    const int h = 1000;
    for (int t = threadIdx.x; t < h; t += NTH) {
        float2* b = sm + t;
        float2 x[16];
#pragma unroll
        for (int q = 0; q < 16; q++) x[q] = b[q * h];
        dft16(x);
        Tw16 tw; tw.init(t);
        b[0] = x[0];
#pragma unroll
        for (int p = 1; p < 16; p++) b[p * h] = cmul(x[p], tw.get(p));
    }
    __syncthreads();
}

template<int NS, int STRIDE>
__device__ __forceinline__ void stage10_fwd(float2* sm) {
    const int h = NS / 10;
    for (int u = threadIdx.x; u < N_FFT / 10; u += NTH) {
        int blk = u / h, t = u - blk * h;
        float2* b = sm + blk * NS + t;
        float2 x[10];
#pragma unroll
        for (int q = 0; q < 10; q++) x[q] = b[q * h];
        dft10(x);
        b[0] = x[0];
        if (NS != 10) {
            Tw10 tw; tw.init(STRIDE * t);
#pragma unroll
            for (int p = 1; p < 10; p++) b[p * h] = cmul(x[p], tw.get(p));
        } else {
#pragma unroll
            for (int p = 1; p < 10; p++) b[p * h] = x[p];
        }
    }
    __syncthreads();
}

// ---------------- inverse FFT stages, 8000 pts (plan: 16,10,10,5) ----------
// Mirrored DIT, scrambled input -> natural order. W_8000^j = g_tw[2j].

__device__ __forceinline__ void stage5_inv8(float2* Y) {
    for (int u = threadIdx.x; u < M_HALF / 5; u += NTH) {
        float2* b = Y + u * 5;
        float2 o[5];
        dft5i(b[0], b[1], b[2], b[3], b[4], o);
#pragma unroll
        for (int q = 0; q < 5; q++) b[q] = o[q];
    }
    __syncthreads();
}

template<int NS, int TWS>   // TWS = 16000 / NS (half-size doubling folded in)
__device__ __forceinline__ void stage10_inv8(float2* Y) {
    const int h = NS / 10;
    for (int u = threadIdx.x; u < M_HALF / 10; u += NTH) {
        int blk = u / h, t = u - blk * h;
        float2* b = Y + blk * NS + t;
        Tw10 tw; tw.init(TWS * t);
        float2 y[10];
        y[0] = b[0];
#pragma unroll
        for (int p = 1; p < 10; p++) y[p] = cmulc(b[p * h], tw.get(p));
        idft10(y);
#pragma unroll
        for (int q = 0; q < 10; q++) b[q * h] = y[q];
    }
    __syncthreads();
}

// Final inverse stage (radix-16 over 8000) fused with de-interleave,
// signed-sqrt output (coalesced float2 stores) and column-norm REDG.
__device__ __forceinline__ void stage16_inv_store8(float2* Y, float* dst) {
    const int h = 500;
    float2* dst2 = (float2*)dst;
    for (int t = threadIdx.x; t < h; t += NTH) {
        float2* b = Y + t;
        Tw16 tw; tw.init(2 * t);
        float2 y[16];
        y[0] = b[0];
#pragma unroll
        for (int p = 1; p < 16; p++) y[p] = cmulc(b[p * h], tw.get(p));
        idft16(y);
#pragma unroll
        for (int q = 0; q < 16; q++) {
            int m = q * 500 + t;           // y[m] = x[2m] + i x[2m+1]
            float c0 = y[q].x, c1 = y[q].y;
            float a0 = fabsf(c0), a1 = fabsf(c1);
            dst2[m] = make_float2(copysignf(sqrtf(a0), c0),
                                  copysignf(sqrtf(a1), c1));
            atomicAdd(&g_norm[2 * m],     a0);   // ss^2 == |c| exactly
            atomicAdd(&g_norm[2 * m + 1], a1);
        }
    }
}

// ------- extract (one block per sketch row) + fused one-time setup ---------
// 128 threads/block: fine-grained early exit (~53% of row scanned on average)
__global__ void k_extract(const float* __restrict__ sk1,
                          const float* __restrict__ sk2) {
    int r = blockIdx.x;

    if (threadIdx.x < 4) {
        int j = r * 4 + threadIdx.x;
        if (j < N_FFT) {
            double a = -2.0 * 3.14159265358979323846 * (double)j / (double)N_FFT;
            double sn, cs;
            sincos(a, &sn, &cs);
            g_tw[j] = make_float2((float)cs, (float)sn);
            g_norm[j] = 0.f;
            // isig for plan {16,10,10,10}
            int p0 = j / 1000, rr = j - p0 * 1000;
            int p1 = rr / 100;  rr -= p1 * 100;
            int p2 = rr / 10,  p3 = rr - (rr / 10) * 10;
            g_isig[p0 + 16 * (p1 + 10 * (p2 + 10 * p3))] = j;
            if (j < M_HALF) {
                // isig8 for plan {16,10,10,5}
                int q0 = j / 500, r8 = j - q0 * 500;
                int q1 = r8 / 50; r8 -= q1 * 50;
                int q2 = r8 / 5,  q3 = r8 - q2 * 5;
                g_isig8[q0 + 16 * (q1 + 10 * (q2 + 10 * q3))] = j;
            }
        }
    }

    const float* row = (r < IN_DIM) ? (sk1 + (size_t)r * N_FFT)
                                    : (sk2 + (size_t)(r - IN_DIM) * N_FFT);
    const float4* row4 = (const float4*)row;
    __shared__ int found;
    if (threadIdx.x == 0) found = 0;
    __syncthreads();
    for (int base = 0; base < N_FFT / 4; base += blockDim.x) {
        int j = base + threadIdx.x;
        if (j < N_FFT / 4) {
            float4 v = row4[j];
            if (v.x != 0.f || v.y != 0.f || v.z != 0.f || v.w != 0.f) {
                int   c   = (v.x != 0.f) ? 0 : (v.y != 0.f) ? 1 : (v.z != 0.f) ? 2 : 3;
                float val = (c == 0) ? v.x : (c == 1) ? v.y : (c == 2) ? v.z : v.w;
                g_h[r] = 4 * j + c;
                g_s[r] = val;
                found = 1;
            }
        }
        __syncthreads();
        if (found) break;
    }
}

// ---------------- fused main kernel ----------------
// smem: [0,16000) Z work array, [16000,24000) Y half-spectrum. 192000 bytes.
__global__ void __launch_bounds__(NTH, 1)
k_main(const float* __restrict__ x1, const float* __restrict__ x2,
       float* __restrict__ out) {
    extern __shared__ float2 sm[];
    float2* Y = sm + N_FFT;
    int b = blockIdx.x;

    float4* sm4 = (float4*)sm;
    for (int i = threadIdx.x; i < N_FFT / 2; i += NTH)
        sm4[i] = make_float4(0.f, 0.f, 0.f, 0.f);
    __syncthreads();

    // count-sketch scatter: p1 -> real, p2 -> imag
    const float* r1 = x1 + (size_t)b * IN_DIM;
    const float* r2 = x2 + (size_t)b * IN_DIM;
    for (int k = threadIdx.x; k < IN_DIM; k += NTH) {
        atomicAdd(&sm[g_h[k]].x,          g_s[k]          * r1[k]);
        atomicAdd(&sm[g_h[IN_DIM + k]].y, g_s[IN_DIM + k] * r2[k]);
    }
    __syncthreads();

    // forward 16000-pt FFT of z = p1 + i p2 (scrambled output)
    stage16_fwd(sm);
    stage10_fwd<1000, 16>(sm);
    stage10_fwd<100, 160>(sm);
    stage10_fwd<10, 1600>(sm);

    // Hermitian split + product + irfft half-size packing, all in one pass.
    // Y[k] = (G[k]+G[k+8000]) + i (G[k]-G[k+8000]) e^{+2pi i k/N},
    // G[k+8000] = conj(G[8000-k]).  Writes go to the scrambled order of the
    // 8000-pt inverse plan. Z reads and Y writes live in disjoint smem.
    for (int k = threadIdx.x; k <= 4000; k += NTH) {
        if (k == 0) {
            float2 z0 = sm[g_isig[0]];
            float2 zn = sm[g_isig[M_HALF]];
            float G0 = z0.x * z0.y;         // F1[0]*F2[0]
            float G8 = zn.x * zn.y;         // F1[8000]*F2[8000]
            Y[g_isig8[0]] = make_float2(G0 + G8, G0 - G8);
        } else if (k == 4000) {
            float2 Zk = sm[g_isig[4000]], Zm = sm[g_isig[12000]];
            float2 F1 = make_float2(0.5f*(Zk.x+Zm.x),  0.5f*(Zk.y-Zm.y));
            float2 F2 = make_float2(0.5f*(Zk.y+Zm.y), -0.5f*(Zk.x-Zm.x));
            float2 G = cmul(F1, F2);
            Y[g_isig8[4000]] = make_float2(2.f * G.x, -2.f * G.y);
        } else {
            int mk = M_HALF - k;
            float2 Zk  = sm[g_isig[k]],  Zmk = sm[g_isig[N_FFT - k]];
            float2 Za  = sm[g_isig[mk]], Zb  = sm[g_isig[M_HALF + k]];
            float2 F1 = make_float2(0.5f*(Zk.x+Zmk.x),  0.5f*(Zk.y-Zmk.y));
            float2 F2 = make_float2(0.5f*(Zk.y+Zmk.y), -0.5f*(Zk.x-Zmk.x));
            float2 Gk = cmul(F1, F2);
            float2 H1 = make_float2(0.5f*(Za.x+Zb.x),  0.5f*(Za.y-Zb.y));
            float2 H2 = make_float2(0.5f*(Za.y+Zb.y), -0.5f*(Za.x-Zb.x));
            float2 Gm = cmul(H1, H2);
            float2 W  = g_tw[k];
            float2 cGm = make_float2(Gm.x, -Gm.y);
            float2 cGk = make_float2(Gk.x, -Gk.y);
            // Y[k]
            float2 A1 = cadd(Gk, cGm);
            float2 B1 = cmulc(csub(Gk, cGm), W);           // * e^{+2pi i k/N}
            Y[g_isig8[k]] = cadd(A1, mul_posi(B1));
            // Y[8000-k]  (e^{+2pi i mk/N} = -W)
            float2 A2 = cadd(Gm, cGk);
            float2 t2 = cmul(csub(Gm, cGk), W);
            Y[g_isig8[mk]] = cadd(A2, mul_posi(make_float2(-t2.x, -t2.y)));
        }
    }
    __syncthreads();

    // 8000-pt inverse (natural order out) fused with de-interleave + store
    stage5_inv8(Y);
    stage10_inv8<50, 320>(Y);
    stage10_inv8<500, 32>(Y);
    stage16_inv_store8(Y, out + (size_t)b * N_FFT);
}

// fused: reciprocal-norm computed in place from the accumulated sums
__global__ void k_normalize(float* __restrict__ out) {
    int c4 = blockIdx.x * blockDim.x + threadIdx.x;
    if (c4 >= N_FFT / 4) return;
    int b = blockIdx.y;
    float4 nv = ((const float4*)g_norm)[c4];
    float rx = 1.0f / fmaxf(sqrtf(nv.x), 1e-12f);
    float ry = 1.0f / fmaxf(sqrtf(nv.y), 1e-12f);
    float rz = 1.0f / fmaxf(sqrtf(nv.z), 1e-12f);
    float rw = 1.0f / fmaxf(sqrtf(nv.w), 1e-12f);
    float4* o4 = (float4*)out + (size_t)b * (N_FFT / 4) + c4;
    float4 v = *o4;
    v.x *= rx; v.y *= ry; v.z *= rz; v.w *= rw;
    *o4 = v;
}

// ---------------- launch ----------------
extern "C" void kernel_launch(void* const* d_in, const int* in_sizes, int n_in,
                              void* d_out, int out_size) {
    const float* x1  = (const float*)d_in[0];
    const float* x2  = (const float*)d_in[1];
    const float* sk1 = (const float*)d_in[2];
    const float* sk2 = (const float*)d_in[3];
    float* out = (float*)d_out;

    const int smem = (N_FFT + M_HALF) * sizeof(float2);  // 192000 B
    cudaFuncSetAttribute(k_main, cudaFuncAttributeMaxDynamicSharedMemorySize, smem);

    k_extract<<<2 * IN_DIM, 128>>>(sk1, sk2);
    k_main<<<BATCH, NTH, smem>>>(x1, x2, out);
    dim3 ng((N_FFT / 4 + 255) / 256, BATCH);
    k_normalize<<<ng, 256>>>(out);
}

// round 12
// speedup vs baseline: 1.3896x; 1.0338x over previous
#include <cuda_runtime.h>
#include <cuda_bf16.h>
#include <math.h>

#define N_FFT 16000
#define M_HALF 8000
#define BATCH 512
#define IN_DIM 2048
#define NTH 1024

// ---------------- scratch (static __device__, no allocation) ----------------
__device__ int    g_h[2 * IN_DIM];
__device__ float  g_s[2 * IN_DIM];
__device__ float2 g_tw[N_FFT];      // W_N^j = exp(-2*pi*i*j/N)
__device__ int    g_isig[N_FFT];    // natural freq -> scrambled pos (plan 16,10,10,10)
__device__ int    g_isig8[M_HALF];  // natural freq -> scrambled pos (plan 16,10,10,5)
__device__ __align__(16) float g_norm[N_FFT];  // sum |c| (column sumsq)

// ---------------- complex helpers ----------------
__device__ __forceinline__ float2 cmul(float2 a, float2 b) {
    return make_float2(a.x * b.x - a.y * b.y, a.x * b.y + a.y * b.x);
}
__device__ __forceinline__ float2 cmulc(float2 a, float2 b) {  // a * conj(b)
    return make_float2(a.x * b.x + a.y * b.y, a.y * b.x - a.x * b.y);
}
__device__ __forceinline__ float2 cadd(float2 a, float2 b) {
    return make_float2(a.x + b.x, a.y + b.y);
}
__device__ __forceinline__ float2 csub(float2 a, float2 b) {
    return make_float2(a.x - b.x, a.y - b.y);
}
__device__ __forceinline__ float2 mul_negi(float2 a) { return make_float2(a.y, -a.x); }
__device__ __forceinline__ float2 mul_posi(float2 a) { return make_float2(-a.y, a.x); }

// W5^j
__constant__ float2 W5c[5] = {
    { 1.0f,                  0.0f                 },
    { 0.30901699437494742f, -0.95105651629515357f },
    {-0.80901699437494742f, -0.58778525229247314f },
    {-0.80901699437494745f,  0.58778525229247312f },
    { 0.30901699437494740f,  0.95105651629515364f }
};
// W10^m, m=0..4
__constant__ float2 W10c[5] = {
    { 1.0f,                  0.0f                 },
    { 0.80901699437494742f, -0.58778525229247312f },
    { 0.30901699437494742f, -0.95105651629515357f },
    {-0.30901699437494742f, -0.95105651629515357f },
    {-0.80901699437494742f, -0.58778525229247312f }
};

#define C_S2 0.70710678118654752440f
#define C16A 0.92387953251128676f
#define C16B 0.38268343236508977f

// ---------------- small DFTs in registers ----------------
#define DFT4F(a,b,c,d,o0,o1,o2,o3) do { \
    float2 _t0 = cadd(a,c), _t1 = csub(a,c); \
    float2 _t2 = cadd(b,d), _t3 = mul_negi(csub(b,d)); \
    o0 = cadd(_t0,_t2); o1 = cadd(_t1,_t3); \
    o2 = csub(_t0,_t2); o3 = csub(_t1,_t3); } while(0)
#define DFT4I(a,b,c,d,o0,o1,o2,o3) do { \
    float2 _t0 = cadd(a,c), _t1 = csub(a,c); \
    float2 _t2 = cadd(b,d), _t3 = mul_posi(csub(b,d)); \
    o0 = cadd(_t0,_t2); o1 = cadd(_t1,_t3); \
    o2 = csub(_t0,_t2); o3 = csub(_t1,_t3); } while(0)

__device__ __forceinline__ void dft16(float2 x[16]) {
    float2 A0[4], A1[4], A2[4], A3[4];
    DFT4F(x[0], x[4], x[8],  x[12], A0[0], A0[1], A0[2], A0[3]);
    DFT4F(x[1], x[5], x[9],  x[13], A1[0], A1[1], A1[2], A1[3]);
    DFT4F(x[2], x[6], x[10], x[14], A2[0], A2[1], A2[2], A2[3]);
    DFT4F(x[3], x[7], x[11], x[15], A3[0], A3[1], A3[2], A3[3]);
    A1[1] = cmul(A1[1], make_float2( C16A, -C16B));
    A1[2] = cmul(A1[2], make_float2( C_S2, -C_S2));
    A1[3] = cmul(A1[3], make_float2( C16B, -C16A));
    A2[1] = cmul(A2[1], make_float2( C_S2, -C_S2));
    A2[2] = mul_negi(A2[2]);
    A2[3] = cmul(A2[3], make_float2(-C_S2, -C_S2));
    A3[1] = cmul(A3[1], make_float2( C16B, -C16A));
    A3[2] = cmul(A3[2], make_float2(-C_S2, -C_S2));
    A3[3] = cmul(A3[3], make_float2(-C16A,  C16B));
#pragma unroll
    for (int m = 0; m < 4; m++)
        DFT4F(A0[m], A1[m], A2[m], A3[m], x[m], x[m+4], x[m+8], x[m+12]);
}

__device__ __forceinline__ void idft16(float2 x[16]) {
    float2 A0[4], A1[4], A2[4], A3[4];
    DFT4I(x[0], x[4], x[8],  x[12], A0[0], A0[1], A0[2], A0[3]);
    DFT4I(x[1], x[5], x[9],  x[13], A1[0], A1[1], A1[2], A1[3]);
    DFT4I(x[2], x[6], x[10], x[14], A2[0], A2[1], A2[2], A2[3]);
    DFT4I(x[3], x[7], x[11], x[15], A3[0], A3[1], A3[2], A3[3]);
    A1[1] = cmul(A1[1], make_float2( C16A,  C16B));
    A1[2] = cmul(A1[2], make_float2( C_S2,  C_S2));
    A1[3] = cmul(A1[3], make_float2( C16B,  C16A));
    A2[1] = cmul(A2[1], make_float2( C_S2,  C_S2));
    A2[2] = mul_posi(A2[2]);
    A2[3] = cmul(A2[3], make_float2(-C_S2,  C_S2));
    A3[1] = cmul(A3[1], make_float2( C16B,  C16A));
    A3[2] = cmul(A3[2], make_float2(-C_S2,  C_S2));
    A3[3] = cmul(A3[3], make_float2(-C16A, -C16B));
#pragma unroll
    for (int m = 0; m < 4; m++)
        DFT4I(A0[m], A1[m], A2[m], A3[m], x[m], x[m+4], x[m+8], x[m+12]);
}

__device__ __forceinline__ void dft5f(float2 a0, float2 a1, float2 a2,
                                      float2 a3, float2 a4, float2 o[5]) {
#pragma unroll
    for (int p = 0; p < 5; p++) {
        float2 acc = a0;
        acc = cadd(acc, cmul(a1, W5c[p % 5]));
        acc = cadd(acc, cmul(a2, W5c[(2*p) % 5]));
        acc = cadd(acc, cmul(a3, W5c[(3*p) % 5]));
        acc = cadd(acc, cmul(a4, W5c[(4*p) % 5]));
        o[p] = acc;
    }
}
__device__ __forceinline__ void dft5i(float2 a0, float2 a1, float2 a2,
                                      float2 a3, float2 a4, float2 o[5]) {
#pragma unroll
    for (int p = 0; p < 5; p++) {
        float2 acc = a0;
        acc = cadd(acc, cmulc(a1, W5c[p % 5]));
        acc = cadd(acc, cmulc(a2, W5c[(2*p) % 5]));
        acc = cadd(acc, cmulc(a3, W5c[(3*p) % 5]));
        acc = cadd(acc, cmulc(a4, W5c[(4*p) % 5]));
        o[p] = acc;
    }
}

__device__ __forceinline__ void dft10(float2 x[10]) {
    float2 B0[5], B1[5];
    dft5f(x[0], x[2], x[4], x[6], x[8], B0);
    dft5f(x[1], x[3], x[5], x[7], x[9], B1);
#pragma unroll
    for (int m = 0; m < 5; m++) {
        float2 t = cmul(B1[m], W10c[m]);
        x[m]     = cadd(B0[m], t);
        x[m + 5] = csub(B0[m], t);
    }
}
__device__ __forceinline__ void idft10(float2 x[10]) {
    float2 B0[5], B1[5];
    dft5i(x[0], x[2], x[4], x[6], x[8], B0);
    dft5i(x[1], x[3], x[5], x[7], x[9], B1);
#pragma unroll
    for (int m = 0; m < 5; m++) {
        float2 t = cmulc(B1[m], W10c[m]);
        x[m]     = cadd(B0[m], t);
        x[m + 5] = csub(B0[m], t);
    }
}

// ------- tree twiddles: ONE global load, depth <= 4, 14 cmuls total --------
struct Tw16t {
    float2 t1, t2, t3, t4, t8, t12;
    __device__ __forceinline__ void init(int s) {
        t1  = g_tw[s];
        t2  = cmul(t1, t1);
        t3  = cmul(t2, t1);
        t4  = cmul(t2, t2);
        t8  = cmul(t4, t4);
        t12 = cmul(t8, t4);
    }
    __device__ __forceinline__ float2 get(int p) const {   // p = 1..15, constant
        switch (p) {
            case 1:  return t1;
            case 2:  return t2;
            case 3:  return t3;
            case 4:  return t4;
            case 5:  return cmul(t4, t1);
            case 6:  return cmul(t4, t2);
            case 7:  return cmul(t4, t3);
            case 8:  return t8;
            case 9:  return cmul(t8, t1);
            case 10: return cmul(t8, t2);
            case 11: return cmul(t8, t3);
            case 12: return t12;
            case 13: return cmul(t12, t1);
            case 14: return cmul(t12, t2);
            default: return cmul(t12, t3);
        }
    }
};
struct Tw10t {
    float2 t1, t2, t3, t4, t5;
    __device__ __forceinline__ void init(int s) {
        t1 = g_tw[s];
        t2 = cmul(t1, t1);
        t3 = cmul(t2, t1);
        t4 = cmul(t2, t2);
        t5 = cmul(t4, t1);
    }
    __device__ __forceinline__ float2 get(int p) const {   // p = 1..9, constant
        switch (p) {
            case 1: return t1;
            case 2: return t2;
            case 3: return t3;
            case 4: return t4;
            case 5: return t5;
            case 6: return cmul(t5, t1);
            case 7: return cmul(t5, t2);
            case 8: return cmul(t5, t3);
            default: return cmul(t5, t4);
        }
    }
};

// ---------------- forward FFT stages, 16000 pts (plan: 16,10,10,10) --------
__device__ __forceinline__ void stage16_fwd(float2* sm) {
    const int h = 1000;
    for (int t = threadIdx.x; t < h; t += NTH) {
        float2* b = sm + t;
        float2 x[16];
#pragma unroll
        for (int q = 0; q < 16; q++) x[q] = b[q * h];
        dft16(x);
        Tw16t tw; tw.init(t);
        b[0] = x[0];
#pragma unroll
        for (int p = 1; p < 16; p++) b[p * h] = cmul(x[p], tw.get(p));
    }
    __syncthreads();
}

template<int NS, int STRIDE>
__device__ __forceinline__ void stage10_fwd(float2* sm) {
    const int h = NS / 10;
    for (int u = threadIdx.x; u < N_FFT / 10; u += NTH) {
        int blk = u / h, t = u - blk * h;
        float2* b = sm + blk * NS + t;
        float2 x[10];
#pragma unroll
        for (int q = 0; q < 10; q++) x[q] = b[q * h];
        dft10(x);
        b[0] = x[0];
        if (NS != 10) {
            Tw10t tw; tw.init(STRIDE * t);
#pragma unroll
            for (int p = 1; p < 10; p++) b[p * h] = cmul(x[p], tw.get(p));
        } else {
#pragma unroll
            for (int p = 1; p < 10; p++) b[p * h] = x[p];
        }
    }
    __syncthreads();
}

// ---------------- inverse FFT stages, 8000 pts (plan: 16,10,10,5) ----------
// Mirrored DIT, scrambled input -> natural order. W_8000^j = g_tw[2j].

__device__ __forceinline__ void stage5_inv8(float2* Y) {
    for (int u = threadIdx.x; u < M_HALF / 5; u += NTH) {
        float2* b = Y + u * 5;
        float2 o[5];
        dft5i(b[0], b[1], b[2], b[3], b[4], o);
#pragma unroll
        for (int q = 0; q < 5; q++) b[q] = o[q];
    }
    __syncthreads();
}

template<int NS, int TWS>   // TWS = 16000 / NS (half-size doubling folded in)
__device__ __forceinline__ void stage10_inv8(float2* Y) {
    const int h = NS / 10;
    for (int u = threadIdx.x; u < M_HALF / 10; u += NTH) {
        int blk = u / h, t = u - blk * h;
        float2* b = Y + blk * NS + t;
        Tw10t tw; tw.init(TWS * t);
        float2 y[10];
        y[0] = b[0];
#pragma unroll
        for (int p = 1; p < 10; p++) y[p] = cmulc(b[p * h], tw.get(p));
        idft10(y);
#pragma unroll
        for (int q = 0; q < 10; q++) b[q * h] = y[q];
    }
    __syncthreads();
}

// Final inverse stage (radix-16 over 8000) fused with de-interleave,
// signed-sqrt output (coalesced float2 stores) and column-norm REDG.
__device__ __forceinline__ void stage16_inv_store8(float2* Y, float* dst) {
    const int h = 500;
    float2* dst2 = (float2*)dst;
    for (int t = threadIdx.x; t < h; t += NTH) {
        float2* b = Y + t;
        Tw16t tw; tw.init(2 * t);
        float2 y[16];
        y[0] = b[0];
#pragma unroll
        for (int p = 1; p < 16; p++) y[p] = cmulc(b[p * h], tw.get(p));
        idft16(y);
#pragma unroll
        for (int q = 0; q < 16; q++) {
            int m = q * 500 + t;           // y[m] = x[2m] + i x[2m+1]
            float c0 = y[q].x, c1 = y[q].y;
            float a0 = fabsf(c0), a1 = fabsf(c1);
            dst2[m] = make_float2(copysignf(sqrtf(a0), c0),
                                  copysignf(sqrtf(a1), c1));
            atomicAdd(&g_norm[2 * m],     a0);   // ss^2 == |c| exactly
            atomicAdd(&g_norm[2 * m + 1], a1);
        }
    }
}

// ------- extract (one block per sketch row) + fused one-time setup ---------
// Barrier-free: volatile flag poll, 4 float4 loads in flight per thread.
__global__ void k_extract(const float* __restrict__ sk1,
                          const float* __restrict__ sk2) {
    int r = blockIdx.x;

    if (threadIdx.x < 4) {
        int j = r * 4 + threadIdx.x;
        if (j < N_FFT) {
            double a = -2.0 * 3.14159265358979323846 * (double)j / (double)N_FFT;
            double sn, cs;
            sincos(a, &sn, &cs);
            g_tw[j] = make_float2((float)cs, (float)sn);
            g_norm[j] = 0.f;
            // isig for plan {16,10,10,10}
            int p0 = j / 1000, rr = j - p0 * 1000;
            int p1 = rr / 100;  rr -= p1 * 100;
            int p2 = rr / 10,  p3 = rr - (rr / 10) * 10;
            g_isig[p0 + 16 * (p1 + 10 * (p2 + 10 * p3))] = j;
            if (j < M_HALF) {
                // isig8 for plan {16,10,10,5}
                int q0 = j / 500, r8 = j - q0 * 500;
                int q1 = r8 / 50; r8 -= q1 * 50;
                int q2 = r8 / 5,  q3 = r8 - q2 * 5;
                g_isig8[q0 + 16 * (q1 + 10 * (q2 + 10 * q3))] = j;
            }
        }
    }

    const float* row = (r < IN_DIM) ? (sk1 + (size_t)r * N_FFT)
                                    : (sk2 + (size_t)(r - IN_DIM) * N_FFT);
    const float4* row4 = (const float4*)row;
    __shared__ int found;
    if (threadIdx.x == 0) found = 0;
    __syncthreads();

    // each iteration: up to 4 independent float4 loads, then flag check
    for (int base = threadIdx.x * 4; base < N_FFT / 4; base += blockDim.x * 4) {
        if (*(volatile int*)&found) return;
#pragma unroll
        for (int q = 0; q < 4; q++) {
            int j = base + q;
            if (j < N_FFT / 4) {
                float4 v = row4[j];
                if (v.x != 0.f || v.y != 0.f || v.z != 0.f || v.w != 0.f) {
                    int   c   = (v.x != 0.f) ? 0 : (v.y != 0.f) ? 1 : (v.z != 0.f) ? 2 : 3;
                    float val = (c == 0) ? v.x : (c == 1) ? v.y : (c == 2) ? v.z : v.w;
                    g_h[r] = 4 * j + c;
                    g_s[r] = val;
                    found = 1;
                    __threadfence_block();
                    return;
                }
            }
        }
    }
}

// ---------------- fused main kernel ----------------
// smem: [0,16000) Z work array, [16000,24000) Y half-spectrum. 192000 bytes.
__global__ void __launch_bounds__(NTH, 1)
k_main(const float* __restrict__ x1, const float* __restrict__ x2,
       float* __restrict__ out) {
    extern __shared__ float2 sm[];
    float2* Y = sm + N_FFT;
    int b = blockIdx.x;

    float4* sm4 = (float4*)sm;
    for (int i = threadIdx.x; i < N_FFT / 2; i += NTH)
        sm4[i] = make_float4(0.f, 0.f, 0.f, 0.f);
    __syncthreads();

    // count-sketch scatter: p1 -> real, p2 -> imag
    const float* r1 = x1 + (size_t)b * IN_DIM;
    const float* r2 = x2 + (size_t)b * IN_DIM;
    for (int k = threadIdx.x; k < IN_DIM; k += NTH) {
        atomicAdd(&sm[g_h[k]].x,          g_s[k]          * r1[k]);
        atomicAdd(&sm[g_h[IN_DIM + k]].y, g_s[IN_DIM + k] * r2[k]);
    }
    __syncthreads();

    // forward 16000-pt FFT of z = p1 + i p2 (scrambled output)
    stage16_fwd(sm);
    stage10_fwd<1000, 16>(sm);
    stage10_fwd<100, 160>(sm);
    stage10_fwd<10, 1600>(sm);

    // Hermitian split + product + irfft half-size packing, all in one pass.
    // Y[k] = (G[k]+G[k+8000]) + i (G[k]-G[k+8000]) e^{+2pi i k/N},
    // G[k+8000] = conj(G[8000-k]).  Writes go to the scrambled order of the
    // 8000-pt inverse plan. Z reads and Y writes live in disjoint smem.
    for (int k = threadIdx.x; k <= 4000; k += NTH) {
        if (k == 0) {
            float2 z0 = sm[g_isig[0]];
            float2 zn = sm[g_isig[M_HALF]];
            float G0 = z0.x * z0.y;         // F1[0]*F2[0]
            float G8 = zn.x * zn.y;         // F1[8000]*F2[8000]
            Y[g_isig8[0]] = make_float2(G0 + G8, G0 - G8);
        } else if (k == 4000) {
            float2 Zk = sm[g_isig[4000]], Zm = sm[g_isig[12000]];
            float2 F1 = make_float2(0.5f*(Zk.x+Zm.x),  0.5f*(Zk.y-Zm.y));
            float2 F2 = make_float2(0.5f*(Zk.y+Zm.y), -0.5f*(Zk.x-Zm.x));
            float2 G = cmul(F1, F2);
            Y[g_isig8[4000]] = make_float2(2.f * G.x, -2.f * G.y);
        } else {
            int mk = M_HALF - k;
            float2 Zk  = sm[g_isig[k]],  Zmk = sm[g_isig[N_FFT - k]];
            float2 Za  = sm[g_isig[mk]], Zb  = sm[g_isig[M_HALF + k]];
            float2 F1 = make_float2(0.5f*(Zk.x+Zmk.x),  0.5f*(Zk.y-Zmk.y));
            float2 F2 = make_float2(0.5f*(Zk.y+Zmk.y), -0.5f*(Zk.x-Zmk.x));
            float2 Gk = cmul(F1, F2);
            float2 H1 = make_float2(0.5f*(Za.x+Zb.x),  0.5f*(Za.y-Zb.y));
            float2 H2 = make_float2(0.5f*(Za.y+Zb.y), -0.5f*(Za.x-Zb.x));
            float2 Gm = cmul(H1, H2);
            float2 W  = g_tw[k];
            float2 cGm = make_float2(Gm.x, -Gm.y);
            float2 cGk = make_float2(Gk.x, -Gk.y);
            // Y[k]
            float2 A1 = cadd(Gk, cGm);
            float2 B1 = cmulc(csub(Gk, cGm), W);           // * e^{+2pi i k/N}
            Y[g_isig8[k]] = cadd(A1, mul_posi(B1));
            // Y[8000-k]  (e^{+2pi i mk/N} = -W)
            float2 A2 = cadd(Gm, cGk);
            float2 t2 = cmul(csub(Gm, cGk), W);
            Y[g_isig8[mk]] = cadd(A2, mul_posi(make_float2(-t2.x, -t2.y)));
        }
    }
    __syncthreads();

    // 8000-pt inverse (natural order out) fused with de-interleave + store
    stage5_inv8(Y);
    stage10_inv8<50, 320>(Y);
    stage10_inv8<500, 32>(Y);
    stage16_inv_store8(Y, out + (size_t)b * N_FFT);
}

// fused: reciprocal-norm computed in place from the accumulated sums
__global__ void k_normalize(float* __restrict__ out) {
    int c4 = blockIdx.x * blockDim.x + threadIdx.x;
    if (c4 >= N_FFT / 4) return;
    int b = blockIdx.y;
    float4 nv = ((const float4*)g_norm)[c4];
    float rx = 1.0f / fmaxf(sqrtf(nv.x), 1e-12f);
    float ry = 1.0f / fmaxf(sqrtf(nv.y), 1e-12f);
    float rz = 1.0f / fmaxf(sqrtf(nv.z), 1e-12f);
    float rw = 1.0f / fmaxf(sqrtf(nv.w), 1e-12f);
    float4* o4 = (float4*)out + (size_t)b * (N_FFT / 4) + c4;
    float4 v = *o4;
    v.x *= rx; v.y *= ry; v.z *= rz; v.w *= rw;
    *o4 = v;
}

// ---------------- launch ----------------
extern "C" void kernel_launch(void* const* d_in, const int* in_sizes, int n_in,
                              void* d_out, int out_size) {
    const float* x1  = (const float*)d_in[0];
    const float* x2  = (const float*)d_in[1];
    const float* sk1 = (const float*)d_in[2];
    const float* sk2 = (const float*)d_in[3];
    float* out = (float*)d_out;

    const int smem = (N_FFT + M_HALF) * sizeof(float2);  // 192000 B
    cudaFuncSetAttribute(k_main, cudaFuncAttributeMaxDynamicSharedMemorySize, smem);

    k_extract<<<2 * IN_DIM, 256>>>(sk1, sk2);
    k_main<<<BATCH, NTH, smem>>>(x1, x2, out);
    dim3 ng((N_FFT / 4 + 255) / 256, BATCH);
    k_normalize<<<ng, 256>>>(out);
}

// round 15
// speedup vs baseline: 1.4978x; 1.0779x over previous
#include <cuda_runtime.h>
#include <cuda_bf16.h>
#include <math.h>

#define N_FFT 16000
#define M_HALF 8000
#define BATCH 512
#define IN_DIM 2048
#define NTH 1024

// ---------------- scratch (static __device__, no allocation) ----------------
__device__ int    g_h[2 * IN_DIM];
__device__ float  g_s[2 * IN_DIM];
__device__ float2 g_tw[N_FFT];      // W_N^j = exp(-2*pi*i*j/N)
__device__ int    g_isig[N_FFT];    // natural freq -> scrambled pos (plan 16,10,10,10)
__device__ int    g_isig8[M_HALF];  // natural freq -> scrambled pos (plan 16,10,10,5)
__device__ __align__(16) float g_norm[N_FFT];  // sum |c| (column sumsq)

// ---------------- complex helpers ----------------
__device__ __forceinline__ float2 cmul(float2 a, float2 b) {
    return make_float2(a.x * b.x - a.y * b.y, a.x * b.y + a.y * b.x);
}
__device__ __forceinline__ float2 cmulc(float2 a, float2 b) {  // a * conj(b)
    return make_float2(a.x * b.x + a.y * b.y, a.y * b.x - a.x * b.y);
}
__device__ __forceinline__ float2 cadd(float2 a, float2 b) {
    return make_float2(a.x + b.x, a.y + b.y);
}
__device__ __forceinline__ float2 csub(float2 a, float2 b) {
    return make_float2(a.x - b.x, a.y - b.y);
}
__device__ __forceinline__ float2 mul_negi(float2 a) { return make_float2(a.y, -a.x); }
__device__ __forceinline__ float2 mul_posi(float2 a) { return make_float2(-a.y, a.x); }

// W5^j
__constant__ float2 W5c[5] = {
    { 1.0f,                  0.0f                 },
    { 0.30901699437494742f, -0.95105651629515357f },
    {-0.80901699437494742f, -0.58778525229247314f },
    {-0.80901699437494745f,  0.58778525229247312f },
    { 0.30901699437494740f,  0.95105651629515364f }
};
// W10^m, m=0..4
__constant__ float2 W10c[5] = {
    { 1.0f,                  0.0f                 },
    { 0.80901699437494742f, -0.58778525229247312f },
    { 0.30901699437494742f, -0.95105651629515357f },
    {-0.30901699437494742f, -0.95105651629515357f },
    {-0.80901699437494742f, -0.58778525229247312f }
};

#define C_S2 0.70710678118654752440f
#define C16A 0.92387953251128676f
#define C16B 0.38268343236508977f

// ---------------- small DFTs in registers ----------------
#define DFT4F(a,b,c,d,o0,o1,o2,o3) do { \
    float2 _t0 = cadd(a,c), _t1 = csub(a,c); \
    float2 _t2 = cadd(b,d), _t3 = mul_negi(csub(b,d)); \
    o0 = cadd(_t0,_t2); o1 = cadd(_t1,_t3); \
    o2 = csub(_t0,_t2); o3 = csub(_t1,_t3); } while(0)
#define DFT4I(a,b,c,d,o0,o1,o2,o3) do { \
    float2 _t0 = cadd(a,c), _t1 = csub(a,c); \
    float2 _t2 = cadd(b,d), _t3 = mul_posi(csub(b,d)); \
    o0 = cadd(_t0,_t2); o1 = cadd(_t1,_t3); \
    o2 = csub(_t0,_t2); o3 = csub(_t1,_t3); } while(0)

__device__ __forceinline__ void dft16(float2 x[16]) {
    float2 A0[4], A1[4], A2[4], A3[4];
    DFT4F(x[0], x[4], x[8],  x[12], A0[0], A0[1], A0[2], A0[3]);
    DFT4F(x[1], x[5], x[9],  x[13], A1[0], A1[1], A1[2], A1[3]);
    DFT4F(x[2], x[6], x[10], x[14], A2[0], A2[1], A2[2], A2[3]);
    DFT4F(x[3], x[7], x[11], x[15], A3[0], A3[1], A3[2], A3[3]);
    A1[1] = cmul(A1[1], make_float2( C16A, -C16B));
    A1[2] = cmul(A1[2], make_float2( C_S2, -C_S2));
    A1[3] = cmul(A1[3], make_float2( C16B, -C16A));
    A2[1] = cmul(A2[1], make_float2( C_S2, -C_S2));
    A2[2] = mul_negi(A2[2]);
    A2[3] = cmul(A2[3], make_float2(-C_S2, -C_S2));
    A3[1] = cmul(A3[1], make_float2( C16B, -C16A));
    A3[2] = cmul(A3[2], make_float2(-C_S2, -C_S2));
    A3[3] = cmul(A3[3], make_float2(-C16A,  C16B));
#pragma unroll
    for (int m = 0; m < 4; m++)
        DFT4F(A0[m], A1[m], A2[m], A3[m], x[m], x[m+4], x[m+8], x[m+12]);
}

__device__ __forceinline__ void idft16(float2 x[16]) {
    float2 A0[4], A1[4], A2[4], A3[4];
    DFT4I(x[0], x[4], x[8],  x[12], A0[0], A0[1], A0[2], A0[3]);
    DFT4I(x[1], x[5], x[9],  x[13], A1[0], A1[1], A1[2], A1[3]);
    DFT4I(x[2], x[6], x[10], x[14], A2[0], A2[1], A2[2], A2[3]);
    DFT4I(x[3], x[7], x[11], x[15], A3[0], A3[1], A3[2], A3[3]);
    A1[1] = cmul(A1[1], make_float2( C16A,  C16B));
    A1[2] = cmul(A1[2], make_float2( C_S2,  C_S2));
    A1[3] = cmul(A1[3], make_float2( C16B,  C16A));
    A2[1] = cmul(A2[1], make_float2( C_S2,  C_S2));
    A2[2] = mul_posi(A2[2]);
    A2[3] = cmul(A2[3], make_float2(-C_S2,  C_S2));
    A3[1] = cmul(A3[1], make_float2( C16B,  C16A));
    A3[2] = cmul(A3[2], make_float2(-C_S2,  C_S2));
    A3[3] = cmul(A3[3], make_float2(-C16A, -C16B));
#pragma unroll
    for (int m = 0; m < 4; m++)
        DFT4I(A0[m], A1[m], A2[m], A3[m], x[m], x[m+4], x[m+8], x[m+12]);
}

__device__ __forceinline__ void dft5f(float2 a0, float2 a1, float2 a2,
                                      float2 a3, float2 a4, float2 o[5]) {
#pragma unroll
    for (int p = 0; p < 5; p++) {
        float2 acc = a0;
        acc = cadd(acc, cmul(a1, W5c[p % 5]));
        acc = cadd(acc, cmul(a2, W5c[(2*p) % 5]));
        acc = cadd(acc, cmul(a3, W5c[(3*p) % 5]));
        acc = cadd(acc, cmul(a4, W5c[(4*p) % 5]));
        o[p] = acc;
    }
}
__device__ __forceinline__ void dft5i(float2 a0, float2 a1, float2 a2,
                                      float2 a3, float2 a4, float2 o[5]) {
#pragma unroll
    for (int p = 0; p < 5; p++) {
        float2 acc = a0;
        acc = cadd(acc, cmulc(a1, W5c[p % 5]));
        acc = cadd(acc, cmulc(a2, W5c[(2*p) % 5]));
        acc = cadd(acc, cmulc(a3, W5c[(3*p) % 5]));
        acc = cadd(acc, cmulc(a4, W5c[(4*p) % 5]));
        o[p] = acc;
    }
}

__device__ __forceinline__ void dft10(float2 x[10]) {
    float2 B0[5], B1[5];
    dft5f(x[0], x[2], x[4], x[6], x[8], B0);
    dft5f(x[1], x[3], x[5], x[7], x[9], B1);
#pragma unroll
    for (int m = 0; m < 5; m++) {
        float2 t = cmul(B1[m], W10c[m]);
        x[m]     = cadd(B0[m], t);
        x[m + 5] = csub(B0[m], t);
    }
}
__device__ __forceinline__ void idft10(float2 x[10]) {
    float2 B0[5], B1[5];
    dft5i(x[0], x[2], x[4], x[6], x[8], B0);
    dft5i(x[1], x[3], x[5], x[7], x[9], B1);
#pragma unroll
    for (int m = 0; m < 5; m++) {
        float2 t = cmulc(B1[m], W10c[m]);
        x[m]     = cadd(B0[m], t);
        x[m + 5] = csub(B0[m], t);
    }
}

// ---------------- forward FFT stages, 16000 pts (plan: 16,10,10,10) --------
// Serial twiddle chains: ONE global load per butterfly, minimal registers
// (the R8 champion configuration — depth is hidden at 32 warps).

__device__ __forceinline__ void stage16_fwd(float2* sm) {
    const int h = 1000;
    for (int t = threadIdx.x; t < h; t += NTH) {
        float2* b = sm + t;
        float2 x[16];
#pragma unroll
        for (int q = 0; q < 16; q++) x[q] = b[q * h];
        dft16(x);
        float2 T = g_tw[t];
        b[0] = x[0];
        float2 cur = T;
#pragma unroll
        for (int p = 1; p < 16; p++) {
            b[p * h] = cmul(x[p], cur);
            cur = cmul(cur, T);
        }
    }
    __syncthreads();
}

template<int NS, int STRIDE>
__device__ __forceinline__ void stage10_fwd(float2* sm) {
    const int h = NS / 10;
    for (int u = threadIdx.x; u < N_FFT / 10; u += NTH) {
        int blk = u / h, t = u - blk * h;
        float2* b = sm + blk * NS + t;
        float2 x[10];
#pragma unroll
        for (int q = 0; q < 10; q++) x[q] = b[q * h];
        dft10(x);
        if (NS != 10) {
            float2 T = g_tw[t * STRIDE];
            float2 cur = T;
#pragma unroll
            for (int p = 1; p < 10; p++) {
                x[p] = cmul(x[p], cur);
                cur = cmul(cur, T);
            }
        }
#pragma unroll
        for (int p = 0; p < 10; p++) b[p * h] = x[p];
    }
    __syncthreads();
}

// ---------------- inverse FFT stages, 8000 pts (plan: 16,10,10,5) ----------
// Mirrored DIT, scrambled input -> natural order. W_8000^j = g_tw[2j].

__device__ __forceinline__ void stage5_inv8(float2* Y) {
    for (int u = threadIdx.x; u < M_HALF / 5; u += NTH) {
        float2* b = Y + u * 5;
        float2 o[5];
        dft5i(b[0], b[1], b[2], b[3], b[4], o);
#pragma unroll
        for (int q = 0; q < 5; q++) b[q] = o[q];
    }
    __syncthreads();
}

template<int NS, int TWS>   // TWS = 16000 / NS (half-size doubling folded in)
__device__ __forceinline__ void stage10_inv8(float2* Y) {
    const int h = NS / 10;
    for (int u = threadIdx.x; u < M_HALF / 10; u += NTH) {
        int blk = u / h, t = u - blk * h;
        float2* b = Y + blk * NS + t;
        float2 y[10];
        y[0] = b[0];
        float2 T = g_tw[TWS * t];
        float2 cur = T;
#pragma unroll
        for (int p = 1; p < 10; p++) {
            y[p] = cmulc(b[p * h], cur);
            cur = cmul(cur, T);
        }
        idft10(y);
#pragma unroll
        for (int q = 0; q < 10; q++) b[q * h] = y[q];
    }
    __syncthreads();
}

// Final inverse stage (radix-16 over 8000) fused with de-interleave,
// signed-sqrt output (coalesced float2 stores) and column-norm REDG.
__device__ __forceinline__ void stage16_inv_store8(float2* Y, float* dst) {
    const int h = 500;
    float2* dst2 = (float2*)dst;
    for (int t = threadIdx.x; t < h; t += NTH) {
        float2* b = Y + t;
        float2 T = g_tw[2 * t];            // W_8000^t
        float2 y[16];
        y[0] = b[0];
        float2 cur = T;
#pragma unroll
        for (int p = 1; p < 16; p++) {
            y[p] = cmulc(b[p * h], cur);
            cur = cmul(cur, T);
        }
        idft16(y);
#pragma unroll
        for (int q = 0; q < 16; q++) {
            int m = q * 500 + t;           // y[m] = x[2m] + i x[2m+1]
            float c0 = y[q].x, c1 = y[q].y;
            float a0 = fabsf(c0), a1 = fabsf(c1);
            dst2[m] = make_float2(copysignf(sqrtf(a0), c0),
                                  copysignf(sqrtf(a1), c1));
            atomicAdd(&g_norm[2 * m],     a0);   // ss^2 == |c| exactly
            atomicAdd(&g_norm[2 * m + 1], a1);
        }
    }
}

// ------- extract (one block per sketch row) + fused one-time setup ---------
// Barriered early-exit (proven volume discipline) with MLP=2 per chunk.
__global__ void k_extract(const float* __restrict__ sk1,
                          const float* __restrict__ sk2) {
    int r = blockIdx.x;

    if (threadIdx.x < 4) {
        int j = r * 4 + threadIdx.x;
        if (j < N_FFT) {
            double a = -2.0 * 3.14159265358979323846 * (double)j / (double)N_FFT;
            double sn, cs;
            sincos(a, &sn, &cs);
            g_tw[j] = make_float2((float)cs, (float)sn);
            g_norm[j] = 0.f;
            // isig for plan {16,10,10,10}
            int p0 = j / 1000, rr = j - p0 * 1000;
            int p1 = rr / 100;  rr -= p1 * 100;
            int p2 = rr / 10,  p3 = rr - (rr / 10) * 10;
            g_isig[p0 + 16 * (p1 + 10 * (p2 + 10 * p3))] = j;
            if (j < M_HALF) {
                // isig8 for plan {16,10,10,5}
                int q0 = j / 500, r8 = j - q0 * 500;
                int q1 = r8 / 50; r8 -= q1 * 50;
                int q2 = r8 / 5,  q3 = r8 - q2 * 5;
                g_isig8[q0 + 16 * (q1 + 10 * (q2 + 10 * q3))] = j;
            }
        }
    }

    const float* row = (r < IN_DIM) ? (sk1 + (size_t)r * N_FFT)
                                    : (sk2 + (size_t)(r - IN_DIM) * N_FFT);
    const float4* row4 = (const float4*)row;
    __shared__ int found;
    if (threadIdx.x == 0) found = 0;
    __syncthreads();

    // chunks of 2 float4 per thread (MLP=2), barrier + early exit per chunk
    for (int base = 0; base < N_FFT / 4; base += 2 * blockDim.x) {
        int j0 = base + threadIdx.x;
        int j1 = j0 + blockDim.x;
        float4 v0 = make_float4(0.f, 0.f, 0.f, 0.f);
        float4 v1 = make_float4(0.f, 0.f, 0.f, 0.f);
        if (j0 < N_FFT / 4) v0 = row4[j0];
        if (j1 < N_FFT / 4) v1 = row4[j1];
        if (v0.x != 0.f || v0.y != 0.f || v0.z != 0.f || v0.w != 0.f) {
            int   c   = (v0.x != 0.f) ? 0 : (v0.y != 0.f) ? 1 : (v0.z != 0.f) ? 2 : 3;
            float val = (c == 0) ? v0.x : (c == 1) ? v0.y : (c == 2) ? v0.z : v0.w;
            g_h[r] = 4 * j0 + c;
            g_s[r] = val;
            found = 1;
        }
        if (v1.x != 0.f || v1.y != 0.f || v1.z != 0.f || v1.w != 0.f) {
            int   c   = (v1.x != 0.f) ? 0 : (v1.y != 0.f) ? 1 : (v1.z != 0.f) ? 2 : 3;
            float val = (c == 0) ? v1.x : (c == 1) ? v1.y : (c == 2) ? v1.z : v1.w;
            g_h[r] = 4 * j1 + c;
            g_s[r] = val;
            found = 1;
        }
        __syncthreads();
        if (found) break;
    }
}

// ---------------- fused main kernel ----------------
// smem: [0,16000) Z work array, [16000,24000) Y half-spectrum. 192000 bytes.
__global__ void __launch_bounds__(NTH, 1)
k_main(const float* __restrict__ x1, const float* __restrict__ x2,
       float* __restrict__ out) {
    extern __shared__ float2 sm[];
    float2* Y = sm + N_FFT;
    int b = blockIdx.x;

    float4* sm4 = (float4*)sm;
    for (int i = threadIdx.x; i < N_FFT / 2; i += NTH)
        sm4[i] = make_float4(0.f, 0.f, 0.f, 0.f);
    __syncthreads();

    // count-sketch scatter: p1 -> real, p2 -> imag
    const float* r1 = x1 + (size_t)b * IN_DIM;
    const float* r2 = x2 + (size_t)b * IN_DIM;
    for (int k = threadIdx.x; k < IN_DIM; k += NTH) {
        atomicAdd(&sm[g_h[k]].x,          g_s[k]          * r1[k]);
        atomicAdd(&sm[g_h[IN_DIM + k]].y, g_s[IN_DIM + k] * r2[k]);
    }
    __syncthreads();

    // forward 16000-pt FFT of z = p1 + i p2 (scrambled output)
    stage16_fwd(sm);
    stage10_fwd<1000, 16>(sm);
    stage10_fwd<100, 160>(sm);
    stage10_fwd<10, 1600>(sm);

    // Hermitian split + product + irfft half-size packing, all in one pass.
    // Y[k] = (G[k]+G[k+8000]) + i (G[k]-G[k+8000]) e^{+2pi i k/N},
    // G[k+8000] = conj(G[8000-k]).  Writes go to the scrambled order of the
    // 8000-pt inverse plan. Z reads and Y writes live in disjoint smem.
    for (int k = threadIdx.x; k <= 4000; k += NTH) {
        if (k == 0) {
            float2 z0 = sm[g_isig[0]];
            float2 zn = sm[g_isig[M_HALF]];
            float G0 = z0.x * z0.y;         // F1[0]*F2[0]
            float G8 = zn.x * zn.y;         // F1[8000]*F2[8000]
            Y[g_isig8[0]] = make_float2(G0 + G8, G0 - G8);
        } else if (k == 4000) {
            float2 Zk = sm[g_isig[4000]], Zm = sm[g_isig[12000]];
            float2 F1 = make_float2(0.5f*(Zk.x+Zm.x),  0.5f*(Zk.y-Zm.y));
            float2 F2 = make_float2(0.5f*(Zk.y+Zm.y), -0.5f*(Zk.x-Zm.x));
            float2 G = cmul(F1, F2);
            Y[g_isig8[4000]] = make_float2(2.f * G.x, -2.f * G.y);
        } else {
            int mk = M_HALF - k;
            float2 Zk  = sm[g_isig[k]],  Zmk = sm[g_isig[N_FFT - k]];
            float2 Za  = sm[g_isig[mk]], Zb  = sm[g_isig[M_HALF + k]];
            float2 F1 = make_float2(0.5f*(Zk.x+Zmk.x),  0.5f*(Zk.y-Zmk.y));
            float2 F2 = make_float2(0.5f*(Zk.y+Zmk.y), -0.5f*(Zk.x-Zmk.x));
            float2 Gk = cmul(F1, F2);
            float2 H1 = make_float2(0.5f*(Za.x+Zb.x),  0.5f*(Za.y-Zb.y));
            float2 H2 = make_float2(0.5f*(Za.y+Zb.y), -0.5f*(Za.x-Zb.x));
            float2 Gm = cmul(H1, H2);
            float2 W  = g_tw[k];
            float2 cGm = make_float2(Gm.x, -Gm.y);
            float2 cGk = make_float2(Gk.x, -Gk.y);
            // Y[k]
            float2 A1 = cadd(Gk, cGm);
            float2 B1 = cmulc(csub(Gk, cGm), W);           // * e^{+2pi i k/N}
            Y[g_isig8[k]] = cadd(A1, mul_posi(B1));
            // Y[8000-k]  (e^{+2pi i mk/N} = -W)
            float2 A2 = cadd(Gm, cGk);
            float2 t2 = cmul(csub(Gm, cGk), W);
            Y[g_isig8[mk]] = cadd(A2, mul_posi(make_float2(-t2.x, -t2.y)));
        }
    }
    __syncthreads();

    // 8000-pt inverse (natural order out) fused with de-interleave + store
    stage5_inv8(Y);
    stage10_inv8<50, 320>(Y);
    stage10_inv8<500, 32>(Y);
    stage16_inv_store8(Y, out + (size_t)b * N_FFT);
}

// fused: reciprocal-norm computed in place from the accumulated sums
__global__ void k_normalize(float* __restrict__ out) {
    int c4 = blockIdx.x * blockDim.x + threadIdx.x;
    if (c4 >= N_FFT / 4) return;
    int b = blockIdx.y;
    float4 nv = ((const float4*)g_norm)[c4];
    float rx = 1.0f / fmaxf(sqrtf(nv.x), 1e-12f);
    float ry = 1.0f / fmaxf(sqrtf(nv.y), 1e-12f);
    float rz = 1.0f / fmaxf(sqrtf(nv.z), 1e-12f);
    float rw = 1.0f / fmaxf(sqrtf(nv.w), 1e-12f);
    float4* o4 = (float4*)out + (size_t)b * (N_FFT / 4) + c4;
    float4 v = *o4;
    v.x *= rx; v.y *= ry; v.z *= rz; v.w *= rw;
    *o4 = v;
}

// ---------------- launch ----------------
extern "C" void kernel_launch(void* const* d_in, const int* in_sizes, int n_in,
                              void* d_out, int out_size) {
    const float* x1  = (const float*)d_in[0];
    const float* x2  = (const float*)d_in[1];
    const float* sk1 = (const float*)d_in[2];
    const float* sk2 = (const float*)d_in[3];
    float* out = (float*)d_out;

    const int smem = (N_FFT + M_HALF) * sizeof(float2);  // 192000 B
    cudaFuncSetAttribute(k_main, cudaFuncAttributeMaxDynamicSharedMemorySize, smem);

    k_extract<<<2 * IN_DIM, 512>>>(sk1, sk2);
    k_main<<<BATCH, NTH, smem>>>(x1, x2, out);
    dim3 ng((N_FFT / 4 + 255) / 256, BATCH);
    k_normalize<<<ng, 256>>>(out);
}

// round 17
// speedup vs baseline: 1.5255x; 1.0185x over previous
#include <cuda_runtime.h>
#include <cuda_bf16.h>
#include <math.h>

#define N_FFT 16000
#define M_HALF 8000
#define BATCH 512
#define IN_DIM 2048
#define NTH 1024

// ---------------- scratch (static __device__, no allocation) ----------------
__device__ int    g_h[2 * IN_DIM];
__device__ float  g_s[2 * IN_DIM];
__device__ float2 g_tw[N_FFT];      // W_N^j = exp(-2*pi*i*j/N)
__device__ int    g_isig[N_FFT];    // natural freq -> scrambled pos (plan 16,10,10,10)
__device__ int    g_isig8[M_HALF];  // natural freq -> scrambled pos (plan 16,10,10,5)
__device__ __align__(16) float g_norm[N_FFT];  // sum |c| (column sumsq)

// ---------------- complex helpers ----------------
__device__ __forceinline__ float2 cmul(float2 a, float2 b) {
    return make_float2(a.x * b.x - a.y * b.y, a.x * b.y + a.y * b.x);
}
__device__ __forceinline__ float2 cmulc(float2 a, float2 b) {  // a * conj(b)
    return make_float2(a.x * b.x + a.y * b.y, a.y * b.x - a.x * b.y);
}
__device__ __forceinline__ float2 cadd(float2 a, float2 b) {
    return make_float2(a.x + b.x, a.y + b.y);
}
__device__ __forceinline__ float2 csub(float2 a, float2 b) {
    return make_float2(a.x - b.x, a.y - b.y);
}
__device__ __forceinline__ float2 mul_negi(float2 a) { return make_float2(a.y, -a.x); }
__device__ __forceinline__ float2 mul_posi(float2 a) { return make_float2(-a.y, a.x); }

// W5^j
__constant__ float2 W5c[5] = {
    { 1.0f,                  0.0f                 },
    { 0.30901699437494742f, -0.95105651629515357f },
    {-0.80901699437494742f, -0.58778525229247314f },
    {-0.80901699437494745f,  0.58778525229247312f },
    { 0.30901699437494740f,  0.95105651629515364f }
};
// W10^m, m=0..4
__constant__ float2 W10c[5] = {
    { 1.0f,                  0.0f                 },
    { 0.80901699437494742f, -0.58778525229247312f },
    { 0.30901699437494742f, -0.95105651629515357f },
    {-0.30901699437494742f, -0.95105651629515357f },
    {-0.80901699437494742f, -0.58778525229247312f }
};

#define C_S2 0.70710678118654752440f
#define C16A 0.92387953251128676f
#define C16B 0.38268343236508977f

// ---------------- small DFTs in registers ----------------
#define DFT4F(a,b,c,d,o0,o1,o2,o3) do { \
    float2 _t0 = cadd(a,c), _t1 = csub(a,c); \
    float2 _t2 = cadd(b,d), _t3 = mul_negi(csub(b,d)); \
    o0 = cadd(_t0,_t2); o1 = cadd(_t1,_t3); \
    o2 = csub(_t0,_t2); o3 = csub(_t1,_t3); } while(0)
#define DFT4I(a,b,c,d,o0,o1,o2,o3) do { \
    float2 _t0 = cadd(a,c), _t1 = csub(a,c); \
    float2 _t2 = cadd(b,d), _t3 = mul_posi(csub(b,d)); \
    o0 = cadd(_t0,_t2); o1 = cadd(_t1,_t3); \
    o2 = csub(_t0,_t2); o3 = csub(_t1,_t3); } while(0)

__device__ __forceinline__ void dft16(float2 x[16]) {
    float2 A0[4], A1[4], A2[4], A3[4];
    DFT4F(x[0], x[4], x[8],  x[12], A0[0], A0[1], A0[2], A0[3]);
    DFT4F(x[1], x[5], x[9],  x[13], A1[0], A1[1], A1[2], A1[3]);
    DFT4F(x[2], x[6], x[10], x[14], A2[0], A2[1], A2[2], A2[3]);
    DFT4F(x[3], x[7], x[11], x[15], A3[0], A3[1], A3[2], A3[3]);
    A1[1] = cmul(A1[1], make_float2( C16A, -C16B));
    A1[2] = cmul(A1[2], make_float2( C_S2, -C_S2));
    A1[3] = cmul(A1[3], make_float2( C16B, -C16A));
    A2[1] = cmul(A2[1], make_float2( C_S2, -C_S2));
    A2[2] = mul_negi(A2[2]);
    A2[3] = cmul(A2[3], make_float2(-C_S2, -C_S2));
    A3[1] = cmul(A3[1], make_float2( C16B, -C16A));
    A3[2] = cmul(A3[2], make_float2(-C_S2, -C_S2));
    A3[3] = cmul(A3[3], make_float2(-C16A,  C16B));
#pragma unroll
    for (int m = 0; m < 4; m++)
        DFT4F(A0[m], A1[m], A2[m], A3[m], x[m], x[m+4], x[m+8], x[m+12]);
}

__device__ __forceinline__ void idft16(float2 x[16]) {
    float2 A0[4], A1[4], A2[4], A3[4];
    DFT4I(x[0], x[4], x[8],  x[12], A0[0], A0[1], A0[2], A0[3]);
    DFT4I(x[1], x[5], x[9],  x[13], A1[0], A1[1], A1[2], A1[3]);
    DFT4I(x[2], x[6], x[10], x[14], A2[0], A2[1], A2[2], A2[3]);
    DFT4I(x[3], x[7], x[11], x[15], A3[0], A3[1], A3[2], A3[3]);
    A1[1] = cmul(A1[1], make_float2( C16A,  C16B));
    A1[2] = cmul(A1[2], make_float2( C_S2,  C_S2));
    A1[3] = cmul(A1[3], make_float2( C16B,  C16A));
    A2[1] = cmul(A2[1], make_float2( C_S2,  C_S2));
    A2[2] = mul_posi(A2[2]);
    A2[3] = cmul(A2[3], make_float2(-C_S2,  C_S2));
    A3[1] = cmul(A3[1], make_float2( C16B,  C16A));
    A3[2] = cmul(A3[2], make_float2(-C_S2,  C_S2));
    A3[3] = cmul(A3[3], make_float2(-C16A, -C16B));
#pragma unroll
    for (int m = 0; m < 4; m++)
        DFT4I(A0[m], A1[m], A2[m], A3[m], x[m], x[m+4], x[m+8], x[m+12]);
}

__device__ __forceinline__ void dft5f(float2 a0, float2 a1, float2 a2,
                                      float2 a3, float2 a4, float2 o[5]) {
#pragma unroll
    for (int p = 0; p < 5; p++) {
        float2 acc = a0;
        acc = cadd(acc, cmul(a1, W5c[p % 5]));
        acc = cadd(acc, cmul(a2, W5c[(2*p) % 5]));
        acc = cadd(acc, cmul(a3, W5c[(3*p) % 5]));
        acc = cadd(acc, cmul(a4, W5c[(4*p) % 5]));
        o[p] = acc;
    }
}
__device__ __forceinline__ void dft5i(float2 a0, float2 a1, float2 a2,
                                      float2 a3, float2 a4, float2 o[5]) {
#pragma unroll
    for (int p = 0; p < 5; p++) {
        float2 acc = a0;
        acc = cadd(acc, cmulc(a1, W5c[p % 5]));
        acc = cadd(acc, cmulc(a2, W5c[(2*p) % 5]));
        acc = cadd(acc, cmulc(a3, W5c[(3*p) % 5]));
        acc = cadd(acc, cmulc(a4, W5c[(4*p) % 5]));
        o[p] = acc;
    }
}

__device__ __forceinline__ void dft10(float2 x[10]) {
    float2 B0[5], B1[5];
    dft5f(x[0], x[2], x[4], x[6], x[8], B0);
    dft5f(x[1], x[3], x[5], x[7], x[9], B1);
#pragma unroll
    for (int m = 0; m < 5; m++) {
        float2 t = cmul(B1[m], W10c[m]);
        x[m]     = cadd(B0[m], t);
        x[m + 5] = csub(B0[m], t);
    }
}
__device__ __forceinline__ void idft10(float2 x[10]) {
    float2 B0[5], B1[5];
    dft5i(x[0], x[2], x[4], x[6], x[8], B0);
    dft5i(x[1], x[3], x[5], x[7], x[9], B1);
#pragma unroll
    for (int m = 0; m < 5; m++) {
        float2 t = cmulc(B1[m], W10c[m]);
        x[m]     = cadd(B0[m], t);
        x[m + 5] = csub(B0[m], t);
    }
}

// ---------------- forward FFT stages, 16000 pts (plan: 16,10,10,10) --------
// Serial twiddle chains: ONE global load per butterfly, minimal registers
// (the champion configuration — chain depth is hidden at 32 warps).

__device__ __forceinline__ void stage16_fwd(float2* sm) {
    const int h = 1000;
    for (int t = threadIdx.x; t < h; t += NTH) {
        float2* b = sm + t;
        float2 x[16];
#pragma unroll
        for (int q = 0; q < 16; q++) x[q] = b[q * h];
        dft16(x);
        float2 T = g_tw[t];
        b[0] = x[0];
        float2 cur = T;
#pragma unroll
        for (int p = 1; p < 16; p++) {
            b[p * h] = cmul(x[p], cur);
            cur = cmul(cur, T);
        }
    }
    __syncthreads();
}

template<int NS, int STRIDE>
__device__ __forceinline__ void stage10_fwd(float2* sm) {
    const int h = NS / 10;
    for (int u = threadIdx.x; u < N_FFT / 10; u += NTH) {
        int blk = u / h, t = u - blk * h;
        float2* b = sm + blk * NS + t;
        float2 x[10];
#pragma unroll
        for (int q = 0; q < 10; q++) x[q] = b[q * h];
        dft10(x);
        if (NS != 10) {
            float2 T = g_tw[t * STRIDE];
            float2 cur = T;
#pragma unroll
            for (int p = 1; p < 10; p++) {
                x[p] = cmul(x[p], cur);
                cur = cmul(cur, T);
            }
        }
#pragma unroll
        for (int p = 0; p < 10; p++) b[p * h] = x[p];
    }
    __syncthreads();
}

// ---------------- inverse FFT stages, 8000 pts (plan: 16,10,10,5) ----------
// Mirrored DIT, scrambled input -> natural order. W_8000^j = g_tw[2j].

__device__ __forceinline__ void stage5_inv8(float2* Y) {
    for (int u = threadIdx.x; u < M_HALF / 5; u += NTH) {
        float2* b = Y + u * 5;
        float2 o[5];
        dft5i(b[0], b[1], b[2], b[3], b[4], o);
#pragma unroll
        for (int q = 0; q < 5; q++) b[q] = o[q];
    }
    __syncthreads();
}

template<int NS, int TWS>   // TWS = 16000 / NS (half-size doubling folded in)
__device__ __forceinline__ void stage10_inv8(float2* Y) {
    const int h = NS / 10;
    for (int u = threadIdx.x; u < M_HALF / 10; u += NTH) {
        int blk = u / h, t = u - blk * h;
        float2* b = Y + blk * NS + t;
        float2 y[10];
        y[0] = b[0];
        float2 T = g_tw[TWS * t];
        float2 cur = T;
#pragma unroll
        for (int p = 1; p < 10; p++) {
            y[p] = cmulc(b[p * h], cur);
            cur = cmul(cur, T);
        }
        idft10(y);
#pragma unroll
        for (int q = 0; q < 10; q++) b[q * h] = y[q];
    }
    __syncthreads();
}

// Final inverse stage (radix-16 over 8000) fused with de-interleave,
// signed-sqrt output (coalesced float2 stores) and column-norm REDG.
__device__ __forceinline__ void stage16_inv_store8(float2* Y, float* dst) {
    const int h = 500;
    float2* dst2 = (float2*)dst;
    for (int t = threadIdx.x; t < h; t += NTH) {
        float2* b = Y + t;
        float2 T = g_tw[2 * t];            // W_8000^t
        float2 y[16];
        y[0] = b[0];
        float2 cur = T;
#pragma unroll
        for (int p = 1; p < 16; p++) {
            y[p] = cmulc(b[p * h], cur);
            cur = cmul(cur, T);
        }
        idft16(y);
#pragma unroll
        for (int q = 0; q < 16; q++) {
            int m = q * 500 + t;           // y[m] = x[2m] + i x[2m+1]
            float c0 = y[q].x, c1 = y[q].y;
            float a0 = fabsf(c0), a1 = fabsf(c1);
            dst2[m] = make_float2(copysignf(sqrtf(a0), c0),
                                  copysignf(sqrtf(a1), c1));
            atomicAdd(&g_norm[2 * m],     a0);   // ss^2 == |c| exactly
            atomicAdd(&g_norm[2 * m + 1], a1);
        }
    }
}

// ------- extract (one block per sketch row) + fused one-time setup ---------
// Barriered early-exit (proven volume discipline), MLP=8:
// 128 threads x 8 float4 per chunk = 4096 floats (same chunk size as R15).
__global__ void k_extract(const float* __restrict__ sk1,
                          const float* __restrict__ sk2) {
    int r = blockIdx.x;

    if (threadIdx.x < 4) {
        int j = r * 4 + threadIdx.x;
        if (j < N_FFT) {
            double a = -2.0 * 3.14159265358979323846 * (double)j / (double)N_FFT;
            double sn, cs;
            sincos(a, &sn, &cs);
            g_tw[j] = make_float2((float)cs, (float)sn);
            g_norm[j] = 0.f;
            // isig for plan {16,10,10,10}
            int p0 = j / 1000, rr = j - p0 * 1000;
            int p1 = rr / 100;  rr -= p1 * 100;
            int p2 = rr / 10,  p3 = rr - (rr / 10) * 10;
            g_isig[p0 + 16 * (p1 + 10 * (p2 + 10 * p3))] = j;
            if (j < M_HALF) {
                // isig8 for plan {16,10,10,5}
                int q0 = j / 500, r8 = j - q0 * 500;
                int q1 = r8 / 50; r8 -= q1 * 50;
                int q2 = r8 / 5,  q3 = r8 - q2 * 5;
                g_isig8[q0 + 16 * (q1 + 10 * (q2 + 10 * q3))] = j;
            }
        }
    }

    const float* row = (r < IN_DIM) ? (sk1 + (size_t)r * N_FFT)
                                    : (sk2 + (size_t)(r - IN_DIM) * N_FFT);
    const float4* row4 = (const float4*)row;
    __shared__ int found;
    if (threadIdx.x == 0) found = 0;
    __syncthreads();

    // chunks of 8 float4 per thread (all loads issued before any check)
    for (int base = 0; base < N_FFT / 4; base += 8 * blockDim.x) {
        float4 v[8];
        int    jj[8];
#pragma unroll
        for (int q = 0; q < 8; q++) {
            jj[q] = base + q * blockDim.x + threadIdx.x;
            v[q] = (jj[q] < N_FFT / 4) ? row4[jj[q]]
                                       : make_float4(0.f, 0.f, 0.f, 0.f);
        }
#pragma unroll
        for (int q = 0; q < 8; q++) {
            float4 w = v[q];
            if (w.x != 0.f || w.y != 0.f || w.z != 0.f || w.w != 0.f) {
                int   c   = (w.x != 0.f) ? 0 : (w.y != 0.f) ? 1 : (w.z != 0.f) ? 2 : 3;
                float val = (c == 0) ? w.x : (c == 1) ? w.y : (c == 2) ? w.z : w.w;
                g_h[r] = 4 * jj[q] + c;
                g_s[r] = val;
                found = 1;
            }
        }
        __syncthreads();
        if (found) break;
    }
}

// ---------------- fused main kernel ----------------
// smem: [0,16000) Z work array, [16000,24000) Y half-spectrum. 192000 bytes.
__global__ void __launch_bounds__(NTH, 1)
k_main(const float* __restrict__ x1, const float* __restrict__ x2,
       float* __restrict__ out) {
    extern __shared__ float2 sm[];
    float2* Y = sm + N_FFT;
    int b = blockIdx.x;

    float4* sm4 = (float4*)sm;
    for (int i = threadIdx.x; i < N_FFT / 2; i += NTH)
        sm4[i] = make_float4(0.f, 0.f, 0.f, 0.f);
    __syncthreads();

    // count-sketch scatter: p1 -> real, p2 -> imag
    const float* r1 = x1 + (size_t)b * IN_DIM;
    const float* r2 = x2 + (size_t)b * IN_DIM;
    for (int k = threadIdx.x; k < IN_DIM; k += NTH) {
        atomicAdd(&sm[g_h[k]].x,          g_s[k]          * r1[k]);
        atomicAdd(&sm[g_h[IN_DIM + k]].y, g_s[IN_DIM + k] * r2[k]);
    }
    __syncthreads();

    // forward 16000-pt FFT of z = p1 + i p2 (scrambled output)
    stage16_fwd(sm);
    stage10_fwd<1000, 16>(sm);
    stage10_fwd<100, 160>(sm);
    stage10_fwd<10, 1600>(sm);

    // Hermitian split + product + irfft half-size packing, all in one pass.
    // Y[k] = (G[k]+G[k+8000]) + i (G[k]-G[k+8000]) e^{+2pi i k/N},
    // G[k+8000] = conj(G[8000-k]).  Writes go to the scrambled order of the
    // 8000-pt inverse plan. Z reads and Y writes live in disjoint smem.
    for (int k = threadIdx.x; k <= 4000; k += NTH) {
        if (k == 0) {
            float2 z0 = sm[g_isig[0]];
            float2 zn = sm[g_isig[M_HALF]];
            float G0 = z0.x * z0.y;         // F1[0]*F2[0]
            float G8 = zn.x * zn.y;         // F1[8000]*F2[8000]
            Y[g_isig8[0]] = make_float2(G0 + G8, G0 - G8);
        } else if (k == 4000) {
            float2 Zk = sm[g_isig[4000]], Zm = sm[g_isig[12000]];
            float2 F1 = make_float2(0.5f*(Zk.x+Zm.x),  0.5f*(Zk.y-Zm.y));
            float2 F2 = make_float2(0.5f*(Zk.y+Zm.y), -0.5f*(Zk.x-Zm.x));
            float2 G = cmul(F1, F2);
            Y[g_isig8[4000]] = make_float2(2.f * G.x, -2.f * G.y);
        } else {
            int mk = M_HALF - k;
            float2 Zk  = sm[g_isig[k]],  Zmk = sm[g_isig[N_FFT - k]];
            float2 Za  = sm[g_isig[mk]], Zb  = sm[g_isig[M_HALF + k]];
            float2 F1 = make_float2(0.5f*(Zk.x+Zmk.x),  0.5f*(Zk.y-Zmk.y));
            float2 F2 = make_float2(0.5f*(Zk.y+Zmk.y), -0.5f*(Zk.x-Zmk.x));
            float2 Gk = cmul(F1, F2);
            float2 H1 = make_float2(0.5f*(Za.x+Zb.x),  0.5f*(Za.y-Zb.y));
            float2 H2 = make_float2(0.5f*(Za.y+Zb.y), -0.5f*(Za.x-Zb.x));
            float2 Gm = cmul(H1, H2);
            float2 W  = g_tw[k];
            float2 cGm = make_float2(Gm.x, -Gm.y);
            float2 cGk = make_float2(Gk.x, -Gk.y);
            // Y[k]
            float2 A1 = cadd(Gk, cGm);
            float2 B1 = cmulc(csub(Gk, cGm), W);           // * e^{+2pi i k/N}
            Y[g_isig8[k]] = cadd(A1, mul_posi(B1));
            // Y[8000-k]  (e^{+2pi i mk/N} = -W)
            float2 A2 = cadd(Gm, cGk);
            float2 t2 = cmul(csub(Gm, cGk), W);
            Y[g_isig8[mk]] = cadd(A2, mul_posi(make_float2(-t2.x, -t2.y)));
        }
    }
    __syncthreads();

    // 8000-pt inverse (natural order out) fused with de-interleave + store
    stage5_inv8(Y);
    stage10_inv8<50, 320>(Y);
    stage10_inv8<500, 32>(Y);
    stage16_inv_store8(Y, out + (size_t)b * N_FFT);
}

// fused reciprocal-norm + scale, MLP=2 (two float4 pairs per thread)
__global__ void k_normalize(float* __restrict__ out) {
    int i = blockIdx.x * blockDim.x + threadIdx.x;   // 0 .. 1999
    if (i >= N_FFT / 8) return;
    int b = blockIdx.y;
    const float4* n4 = (const float4*)g_norm;
    float4* o4 = (float4*)out + (size_t)b * (N_FFT / 4);
    // issue all four loads up front
    float4 nv0 = n4[i];
    float4 nv1 = n4[i + N_FFT / 8];
    float4 v0 = o4[i];
    float4 v1 = o4[i + N_FFT / 8];
    v0.x *= 1.0f / fmaxf(sqrtf(nv0.x), 1e-12f);
    v0.y *= 1.0f / fmaxf(sqrtf(nv0.y), 1e-12f);
    v0.z *= 1.0f / fmaxf(sqrtf(nv0.z), 1e-12f);
    v0.w *= 1.0f / fmaxf(sqrtf(nv0.w), 1e-12f);
    v1.x *= 1.0f / fmaxf(sqrtf(nv1.x), 1e-12f);
    v1.y *= 1.0f / fmaxf(sqrtf(nv1.y), 1e-12f);
    v1.z *= 1.0f / fmaxf(sqrtf(nv1.z), 1e-12f);
    v1.w *= 1.0f / fmaxf(sqrtf(nv1.w), 1e-12f);
    o4[i] = v0;
    o4[i + N_FFT / 8] = v1;
}

// ---------------- launch ----------------
extern "C" void kernel_launch(void* const* d_in, const int* in_sizes, int n_in,
                              void* d_out, int out_size) {
    const float* x1  = (const float*)d_in[0];
    const float* x2  = (const float*)d_in[1];
    const float* sk1 = (const float*)d_in[2];
    const float* sk2 = (const float*)d_in[3];
    float* out = (float*)d_out;

    const int smem = (N_FFT + M_HALF) * sizeof(float2);  // 192000 B
    cudaFuncSetAttribute(k_main, cudaFuncAttributeMaxDynamicSharedMemorySize, smem);

    k_extract<<<2 * IN_DIM, 128>>>(sk1, sk2);
    k_main<<<BATCH, NTH, smem>>>(x1, x2, out);
    dim3 ng((N_FFT / 8 + 255) / 256, BATCH);
    k_normalize<<<ng, 256>>>(out);
}